// round 4
// baseline (speedup 1.0000x reference)
#include <cuda_runtime.h>
#include <math.h>

#define NN 50000
#define NE 800000
#define TE (NE + NN)          // edges + self loops
#define IN_DIM 128
#define HH 256                // HEADS*HID
#define ODIM 128
#define NEG_SLOPE 0.2f

// ---------------- scratch (device globals; no allocs allowed) ----------------
__device__ __align__(16) float    g_h1[(size_t)NN * HH];     // layer1 projection
__device__ __align__(16) float    g_agg1[(size_t)NN * HH];   // layer1 aggregate -> elu -> h2
__device__ __align__(16) float    g_h2p[(size_t)NN * ODIM];  // layer2 projection
__device__ __align__(16) float    g_as1[NN * 4];
__device__ __align__(16) float    g_ad1[NN * 4];
__device__ __align__(16) unsigned g_m1[NN * 4];
__device__ __align__(16) float    g_den1[NN * 4];
__device__ __align__(16) float    g_ea1[(size_t)TE * 4];
__device__ __align__(16) float    g_as2[NN];
__device__ __align__(16) float    g_ad2[NN];
__device__ __align__(16) unsigned g_m2[NN];
__device__ __align__(16) float    g_den2[NN];
__device__ __align__(16) float    g_ea2[TE];

// ---------------- helpers ----------------
__device__ __forceinline__ unsigned fmap(float f) {
    unsigned u = __float_as_uint(f);
    return (u & 0x80000000u) ? ~u : (u | 0x80000000u);
}
__device__ __forceinline__ float funmap(unsigned u) {
    return __uint_as_float((u & 0x80000000u) ? (u & 0x7FFFFFFFu) : ~u);
}
__device__ __forceinline__ void red_add_v4(float* p, float4 v) {
    asm volatile("red.global.add.v4.f32 [%0], {%1, %2, %3, %4};"
                 :: "l"(p), "f"(v.x), "f"(v.y), "f"(v.z), "f"(v.w) : "memory");
}
__device__ __forceinline__ float warp_sum(float v) {
    #pragma unroll
    for (int off = 16; off; off >>= 1) v += __shfl_xor_sync(0xffffffffu, v, off);
    return v;
}
// load edge endpoints (int32 indices!) with defensive clamp
__device__ __forceinline__ bool edge_sd(int e, const int* __restrict__ src,
                                        const int* __restrict__ dst, int& s, int& d) {
    if (e < NE) { s = src[e]; d = dst[e]; } else { s = d = e - NE; }
    return ((unsigned)s < (unsigned)NN) && ((unsigned)d < (unsigned)NN);
}

// ---------------- GEMM: C[n,M] = A[n,K] @ B[K,M] ----------------
// 64x64 tile, BK=16, 256 threads, 4x4 register blocking.
__global__ __launch_bounds__(256) void gemm_kernel(
    const float* __restrict__ A, const float* __restrict__ B,
    float* __restrict__ C, int n, int K, int M)
{
    __shared__ float sA[16][64];   // [kk][row]
    __shared__ float sB[16][64];   // [kk][col]
    int tid = threadIdx.x;
    int tc = tid & 15;             // col group (4 cols)
    int tr = tid >> 4;             // row group (4 rows)
    int row0 = blockIdx.x * 64;
    int col0 = blockIdx.y * 64;

    float4 acc[4];
    #pragma unroll
    for (int i = 0; i < 4; i++) acc[i] = make_float4(0.f, 0.f, 0.f, 0.f);

    for (int k0 = 0; k0 < K; k0 += 16) {
        #pragma unroll
        for (int i = tid; i < 64 * 16; i += 256) {
            int r = i >> 4, kk = i & 15;
            int gr = row0 + r;
            sA[kk][r] = (gr < n) ? A[(size_t)gr * K + k0 + kk] : 0.f;
        }
        #pragma unroll
        for (int i = tid; i < 16 * 64; i += 256) {
            int kk = i >> 6, c = i & 63;
            sB[kk][c] = B[(size_t)(k0 + kk) * M + col0 + c];
        }
        __syncthreads();
        #pragma unroll
        for (int kk = 0; kk < 16; kk++) {
            float4 b = *(const float4*)&sB[kk][tc * 4];
            #pragma unroll
            for (int i = 0; i < 4; i++) {
                float a = sA[kk][tr * 4 + i];
                acc[i].x += a * b.x; acc[i].y += a * b.y;
                acc[i].z += a * b.z; acc[i].w += a * b.w;
            }
        }
        __syncthreads();
    }
    #pragma unroll
    for (int i = 0; i < 4; i++) {
        int row = row0 + tr * 4 + i;
        if (row < n)
            *(float4*)&C[(size_t)row * M + col0 + tc * 4] = acc[i];
    }
}

// ---------------- per-node attention scalars, layer 1 (4 heads) ----------------
__global__ __launch_bounds__(256) void alpha1_kernel(
    const float* __restrict__ a_src, const float* __restrict__ a_dst)
{
    int node = (blockIdx.x * blockDim.x + threadIdx.x) >> 5;
    int lane = threadIdx.x & 31;
    if (node >= NN) return;
    const float* h = &g_h1[(size_t)node * HH];
    float s[4] = {0, 0, 0, 0}, d[4] = {0, 0, 0, 0};
    #pragma unroll
    for (int k = 0; k < 8; k++) {
        int c = lane + 32 * k;
        float hv = h[c];
        s[k >> 1] += hv * a_src[c];
        d[k >> 1] += hv * a_dst[c];
    }
    #pragma unroll
    for (int hh = 0; hh < 4; hh++) { s[hh] = warp_sum(s[hh]); d[hh] = warp_sum(d[hh]); }
    if (lane == 0) {
        #pragma unroll
        for (int hh = 0; hh < 4; hh++) {
            g_as1[node * 4 + hh] = s[hh];
            g_ad1[node * 4 + hh] = d[hh];
        }
    }
}

// ---------------- per-node attention scalars, layer 2 (1 head) ----------------
__global__ __launch_bounds__(256) void alpha2_kernel(
    const float* __restrict__ a_src, const float* __restrict__ a_dst)
{
    int node = (blockIdx.x * blockDim.x + threadIdx.x) >> 5;
    int lane = threadIdx.x & 31;
    if (node >= NN) return;
    const float* h = &g_h2p[(size_t)node * ODIM];
    float s = 0.f, d = 0.f;
    #pragma unroll
    for (int k = 0; k < 4; k++) {
        int c = lane + 32 * k;
        float hv = h[c];
        s += hv * a_src[c];
        d += hv * a_dst[c];
    }
    s = warp_sum(s); d = warp_sum(d);
    if (lane == 0) { g_as2[node] = s; g_ad2[node] = d; }
}

// ---------------- edge pass A: logits + segment max (layer1) ----------------
__global__ __launch_bounds__(256) void passA1(
    const int* __restrict__ src, const int* __restrict__ dst)
{
    int e = blockIdx.x * blockDim.x + threadIdx.x;
    if (e >= TE) return;
    int s, d;
    if (!edge_sd(e, src, dst, s, d)) return;
    #pragma unroll
    for (int h = 0; h < 4; h++) {
        float v = g_as1[s * 4 + h] + g_ad1[d * 4 + h];
        v = v > 0.f ? v : NEG_SLOPE * v;
        g_ea1[(size_t)e * 4 + h] = v;           // stash logit for pass B
        atomicMax(&g_m1[d * 4 + h], fmap(v));
    }
}

// ---------------- edge pass B: exp + denom (layer1) ----------------
__global__ __launch_bounds__(256) void passB1(
    const int* __restrict__ src, const int* __restrict__ dst)
{
    int e = blockIdx.x * blockDim.x + threadIdx.x;
    if (e >= TE) return;
    int s, d;
    if (!edge_sd(e, src, dst, s, d)) return;
    #pragma unroll
    for (int h = 0; h < 4; h++) {
        float v = g_ea1[(size_t)e * 4 + h];
        float p = __expf(v - funmap(g_m1[d * 4 + h]));
        g_ea1[(size_t)e * 4 + h] = p;
        atomicAdd(&g_den1[d * 4 + h], p);
    }
}

// ---------------- edge pass C: weighted aggregate (layer1, 256 feats) --------
__global__ __launch_bounds__(256) void passC1(
    const int* __restrict__ src, const int* __restrict__ dst)
{
    int gw = (blockIdx.x * blockDim.x + threadIdx.x) >> 5;
    int lane = threadIdx.x & 31;
    if (gw >= TE) return;
    int s, d;
    if (!edge_sd(gw, src, dst, s, d)) return;
    int ha = lane >> 4;        // head of float4 #lane
    int hb = ha + 2;           // head of float4 #(lane+32)
    float wa = g_ea1[(size_t)gw * 4 + ha] / (g_den1[d * 4 + ha] + 1e-16f);
    float wb = g_ea1[(size_t)gw * 4 + hb] / (g_den1[d * 4 + hb] + 1e-16f);
    const float4* hr = (const float4*)&g_h1[(size_t)s * HH];
    float4 va = hr[lane];
    float4 vb = hr[lane + 32];
    va.x *= wa; va.y *= wa; va.z *= wa; va.w *= wa;
    vb.x *= wb; vb.y *= wb; vb.z *= wb; vb.w *= wb;
    float* ag = &g_agg1[(size_t)d * HH];
    red_add_v4(ag + lane * 4, va);
    red_add_v4(ag + (lane + 32) * 4, vb);
}

// ---------------- bias + ELU (layer1 output -> layer2 input, in place) -------
__global__ __launch_bounds__(256) void post1_kernel(const float* __restrict__ b1)
{
    int i = blockIdx.x * blockDim.x + threadIdx.x;
    if (i >= NN * HH) return;
    float v = g_agg1[i] + b1[i & (HH - 1)];
    g_agg1[i] = v > 0.f ? v : (__expf(v) - 1.f);
}

// ---------------- edge pass A/B layer2 (1 head) ----------------
__global__ __launch_bounds__(256) void passA2(
    const int* __restrict__ src, const int* __restrict__ dst)
{
    int e = blockIdx.x * blockDim.x + threadIdx.x;
    if (e >= TE) return;
    int s, d;
    if (!edge_sd(e, src, dst, s, d)) return;
    float v = g_as2[s] + g_ad2[d];
    v = v > 0.f ? v : NEG_SLOPE * v;
    g_ea2[e] = v;                               // stash logit for pass B
    atomicMax(&g_m2[d], fmap(v));
}

__global__ __launch_bounds__(256) void passB2(
    const int* __restrict__ src, const int* __restrict__ dst)
{
    int e = blockIdx.x * blockDim.x + threadIdx.x;
    if (e >= TE) return;
    int s, d;
    if (!edge_sd(e, src, dst, s, d)) return;
    float v = g_ea2[e];
    float p = __expf(v - funmap(g_m2[d]));
    g_ea2[e] = p;
    atomicAdd(&g_den2[d], p);
}

// ---------------- edge pass C layer2 (128 feats) into d_out ------------------
__global__ __launch_bounds__(256) void passC2(
    const int* __restrict__ src, const int* __restrict__ dst,
    float* __restrict__ out)
{
    int gw = (blockIdx.x * blockDim.x + threadIdx.x) >> 5;
    int lane = threadIdx.x & 31;
    if (gw >= TE) return;
    int s, d;
    if (!edge_sd(gw, src, dst, s, d)) return;
    float w = g_ea2[gw] / (g_den2[d] + 1e-16f);
    const float4* hr = (const float4*)&g_h2p[(size_t)s * ODIM];
    float4 v = hr[lane];
    v.x *= w; v.y *= w; v.z *= w; v.w *= w;
    red_add_v4(out + (size_t)d * ODIM + lane * 4, v);
}

// ---------------- final: + b2, L2 normalize rows ----------------
__global__ __launch_bounds__(256) void finalize_kernel(
    float* __restrict__ out, const float* __restrict__ b2)
{
    int node = (blockIdx.x * blockDim.x + threadIdx.x) >> 5;
    int lane = threadIdx.x & 31;
    if (node >= NN) return;
    float4* o = (float4*)(out + (size_t)node * ODIM);
    float4 v = o[lane];
    const float4* bb = (const float4*)b2;
    float4 b = bb[lane];
    v.x += b.x; v.y += b.y; v.z += b.z; v.w += b.w;
    float ss = v.x * v.x + v.y * v.y + v.z * v.z + v.w * v.w;
    ss = warp_sum(ss);
    float sc = 1.f / fmaxf(sqrtf(ss), 1e-12f);
    v.x *= sc; v.y *= sc; v.z *= sc; v.w *= sc;
    o[lane] = v;
}

// ---------------- host ----------------
extern "C" void kernel_launch(void* const* d_in, const int* in_sizes, int n_in,
                              void* d_out, int out_size)
{
    const float* x      = (const float*)d_in[0];
    const int*   ei     = (const int*)d_in[1];     // int32! (JAX x64 disabled)
    const float* W1     = (const float*)d_in[2];
    const float* a_src1 = (const float*)d_in[3];
    const float* a_dst1 = (const float*)d_in[4];
    const float* b1     = (const float*)d_in[5];
    const float* W2     = (const float*)d_in[6];
    const float* a_src2 = (const float*)d_in[7];
    const float* a_dst2 = (const float*)d_in[8];
    const float* b2     = (const float*)d_in[9];
    float*       out    = (float*)d_out;
    const int*   srcp   = ei;
    const int*   dstp   = ei + NE;

    void *p_h1, *p_agg1, *p_h2p, *p_m1, *p_den1, *p_m2, *p_den2;
    cudaGetSymbolAddress(&p_h1,   g_h1);
    cudaGetSymbolAddress(&p_agg1, g_agg1);
    cudaGetSymbolAddress(&p_h2p,  g_h2p);
    cudaGetSymbolAddress(&p_m1,   g_m1);
    cudaGetSymbolAddress(&p_den1, g_den1);
    cudaGetSymbolAddress(&p_m2,   g_m2);
    cudaGetSymbolAddress(&p_den2, g_den2);

    cudaStream_t st = 0;
    cudaMemsetAsync(p_m1,   0, sizeof(unsigned) * NN * 4, st);
    cudaMemsetAsync(p_den1, 0, sizeof(float) * NN * 4, st);
    cudaMemsetAsync(p_agg1, 0, sizeof(float) * (size_t)NN * HH, st);
    cudaMemsetAsync(p_m2,   0, sizeof(unsigned) * NN, st);
    cudaMemsetAsync(p_den2, 0, sizeof(float) * NN, st);
    cudaMemsetAsync(out,    0, sizeof(float) * (size_t)NN * ODIM, st);

    // ---- layer 1 ----
    gemm_kernel<<<dim3(782, 4), 256, 0, st>>>(x, W1, (float*)p_h1, NN, IN_DIM, HH);
    alpha1_kernel<<<(NN * 32 + 255) / 256, 256, 0, st>>>(a_src1, a_dst1);
    passA1<<<(TE + 255) / 256, 256, 0, st>>>(srcp, dstp);
    passB1<<<(TE + 255) / 256, 256, 0, st>>>(srcp, dstp);
    passC1<<<((size_t)TE * 32 + 255) / 256, 256, 0, st>>>(srcp, dstp);
    post1_kernel<<<(NN * HH + 255) / 256, 256, 0, st>>>(b1);

    // ---- layer 2 ----
    gemm_kernel<<<dim3(782, 2), 256, 0, st>>>((const float*)p_agg1, W2,
                                              (float*)p_h2p, NN, HH, ODIM);
    alpha2_kernel<<<(NN * 32 + 255) / 256, 256, 0, st>>>(a_src2, a_dst2);
    passA2<<<(TE + 255) / 256, 256, 0, st>>>(srcp, dstp);
    passB2<<<(TE + 255) / 256, 256, 0, st>>>(srcp, dstp);
    passC2<<<((size_t)TE * 32 + 255) / 256, 256, 0, st>>>(srcp, dstp, out);

    // ---- normalize ----
    finalize_kernel<<<(NN * 32 + 255) / 256, 256, 0, st>>>(out, b2);
}

// round 8
// speedup vs baseline: 1.4294x; 1.4294x over previous
#include <cuda_runtime.h>
#include <math.h>

#define NN 50000
#define NE 800000
#define TE (NE + NN)          // edges + self loops
#define IN_DIM 128
#define HH 256                // HEADS*HID
#define ODIM 128
#define NEG_SLOPE 0.2f

// ---------------- scratch (device globals; no allocs allowed) ----------------
__device__ __align__(16) float g_h1[(size_t)NN * HH];     // layer1 projection
__device__ __align__(16) float g_agg1[(size_t)NN * HH];   // layer1 out (post ELU) = layer2 in
__device__ __align__(16) float g_h2p[(size_t)NN * ODIM];  // layer2 projection
__device__ __align__(16) float g_as1[NN * 4];
__device__ __align__(16) float g_ad1[NN * 4];
__device__ __align__(16) float g_as2[NN];
__device__ __align__(16) float g_ad2[NN];
// CSR (by destination node)
__device__ int g_deg[NN];
__device__ int g_off[NN + 1];
__device__ int g_cur[NN];
__device__ int g_csr_src[TE];

// ---------------- helpers ----------------
__device__ __forceinline__ float warp_sum(float v) {
    #pragma unroll
    for (int off = 16; off; off >>= 1) v += __shfl_xor_sync(0xffffffffu, v, off);
    return v;
}
__device__ __forceinline__ float warp_max(float v) {
    #pragma unroll
    for (int off = 16; off; off >>= 1) v = fmaxf(v, __shfl_xor_sync(0xffffffffu, v, off));
    return v;
}
__device__ __forceinline__ float lrelu(float v) {
    return v > 0.f ? v : NEG_SLOPE * v;
}
// edge endpoints (int32 indices) with defensive clamp
__device__ __forceinline__ bool edge_sd(int e, const int* __restrict__ src,
                                        const int* __restrict__ dst, int& s, int& d) {
    if (e < NE) { s = src[e]; d = dst[e]; } else { s = d = e - NE; }
    return ((unsigned)s < (unsigned)NN) && ((unsigned)d < (unsigned)NN);
}

// ================= CSR build =================
__global__ __launch_bounds__(256) void hist_kernel(
    const int* __restrict__ src, const int* __restrict__ dst)
{
    int e = blockIdx.x * blockDim.x + threadIdx.x;
    if (e >= TE) return;
    int s, d;
    if (!edge_sd(e, src, dst, s, d)) return;
    atomicAdd(&g_deg[d], 1);
}

// single-block exclusive scan over g_deg -> g_off, g_cur
__global__ __launch_bounds__(1024) void scan_kernel()
{
    __shared__ int sh[1024];
    int tid = threadIdx.x;
    int carry = 0;
    const int nchunks = (NN + 1023) / 1024;
    for (int c = 0; c < nchunks; c++) {
        int i = c * 1024 + tid;
        int v = (i < NN) ? g_deg[i] : 0;
        sh[tid] = v;
        __syncthreads();
        #pragma unroll
        for (int off = 1; off < 1024; off <<= 1) {
            int t = (tid >= off) ? sh[tid - off] : 0;
            __syncthreads();
            sh[tid] += t;
            __syncthreads();
        }
        int incl = sh[tid];
        if (i < NN) {
            int o = carry + incl - v;
            g_off[i] = o;
            g_cur[i] = o;
        }
        carry += sh[1023];
        __syncthreads();
    }
    if (tid == 0) g_off[NN] = carry;
}

__global__ __launch_bounds__(256) void scatter_kernel(
    const int* __restrict__ src, const int* __restrict__ dst)
{
    int e = blockIdx.x * blockDim.x + threadIdx.x;
    if (e >= TE) return;
    int s, d;
    if (!edge_sd(e, src, dst, s, d)) return;
    int pos = atomicAdd(&g_cur[d], 1);
    g_csr_src[pos] = s;
}

// ================= GEMM: C[n,M] = A[n,K] @ B[K,M] =================
// 64x64 tile, BK=16, 256 threads, 4x4 register blocking.
__global__ __launch_bounds__(256) void gemm_kernel(
    const float* __restrict__ A, const float* __restrict__ B,
    float* __restrict__ C, int n, int K, int M)
{
    __shared__ float sA[16][64];   // [kk][row]
    __shared__ float sB[16][64];   // [kk][col]
    int tid = threadIdx.x;
    int tc = tid & 15;
    int tr = tid >> 4;
    int row0 = blockIdx.x * 64;
    int col0 = blockIdx.y * 64;

    float4 acc[4];
    #pragma unroll
    for (int i = 0; i < 4; i++) acc[i] = make_float4(0.f, 0.f, 0.f, 0.f);

    for (int k0 = 0; k0 < K; k0 += 16) {
        #pragma unroll
        for (int i = tid; i < 64 * 16; i += 256) {
            int r = i >> 4, kk = i & 15;
            int gr = row0 + r;
            sA[kk][r] = (gr < n) ? A[(size_t)gr * K + k0 + kk] : 0.f;
        }
        #pragma unroll
        for (int i = tid; i < 16 * 64; i += 256) {
            int kk = i >> 6, c = i & 63;
            sB[kk][c] = B[(size_t)(k0 + kk) * M + col0 + c];
        }
        __syncthreads();
        #pragma unroll
        for (int kk = 0; kk < 16; kk++) {
            float4 b = *(const float4*)&sB[kk][tc * 4];
            #pragma unroll
            for (int i = 0; i < 4; i++) {
                float a = sA[kk][tr * 4 + i];
                acc[i].x += a * b.x; acc[i].y += a * b.y;
                acc[i].z += a * b.z; acc[i].w += a * b.w;
            }
        }
        __syncthreads();
    }
    #pragma unroll
    for (int i = 0; i < 4; i++) {
        int row = row0 + tr * 4 + i;
        if (row < n)
            *(float4*)&C[(size_t)row * M + col0 + tc * 4] = acc[i];
    }
}

// ================= per-node attention scalars =================
__global__ __launch_bounds__(256) void alpha1_kernel(
    const float* __restrict__ a_src, const float* __restrict__ a_dst)
{
    int node = (blockIdx.x * blockDim.x + threadIdx.x) >> 5;
    int lane = threadIdx.x & 31;
    if (node >= NN) return;
    const float* h = &g_h1[(size_t)node * HH];
    float s[4] = {0, 0, 0, 0}, d[4] = {0, 0, 0, 0};
    #pragma unroll
    for (int k = 0; k < 8; k++) {
        int c = lane + 32 * k;
        float hv = h[c];
        s[k >> 1] += hv * a_src[c];
        d[k >> 1] += hv * a_dst[c];
    }
    #pragma unroll
    for (int hh = 0; hh < 4; hh++) { s[hh] = warp_sum(s[hh]); d[hh] = warp_sum(d[hh]); }
    if (lane == 0) {
        #pragma unroll
        for (int hh = 0; hh < 4; hh++) {
            g_as1[node * 4 + hh] = s[hh];
            g_ad1[node * 4 + hh] = d[hh];
        }
    }
}

__global__ __launch_bounds__(256) void alpha2_kernel(
    const float* __restrict__ a_src, const float* __restrict__ a_dst)
{
    int node = (blockIdx.x * blockDim.x + threadIdx.x) >> 5;
    int lane = threadIdx.x & 31;
    if (node >= NN) return;
    const float* h = &g_h2p[(size_t)node * ODIM];
    float s = 0.f, d = 0.f;
    #pragma unroll
    for (int k = 0; k < 4; k++) {
        int c = lane + 32 * k;
        float hv = h[c];
        s += hv * a_src[c];
        d += hv * a_dst[c];
    }
    s = warp_sum(s); d = warp_sum(d);
    if (lane == 0) { g_as2[node] = s; g_ad2[node] = d; }
}

// ================= fused layer1: softmax + aggregate + bias + ELU =================
// one warp per destination node
__global__ __launch_bounds__(256) void agg1_kernel(const float* __restrict__ b1)
{
    int node = blockIdx.x * 8 + (threadIdx.x >> 5);
    int lane = threadIdx.x & 31;
    if (node >= NN) return;
    int beg = g_off[node], end = g_off[node + 1];

    float4 ad = *(const float4*)&g_ad1[node * 4];

    // pass 1: segment max per head (edges partitioned across lanes)
    float m0 = -1e30f, m1 = -1e30f, m2 = -1e30f, m3 = -1e30f;
    for (int i = beg + lane; i < end; i += 32) {
        int s = g_csr_src[i];
        float4 as = *(const float4*)&g_as1[s * 4];
        m0 = fmaxf(m0, lrelu(as.x + ad.x));
        m1 = fmaxf(m1, lrelu(as.y + ad.y));
        m2 = fmaxf(m2, lrelu(as.z + ad.z));
        m3 = fmaxf(m3, lrelu(as.w + ad.w));
    }
    m0 = warp_max(m0); m1 = warp_max(m1); m2 = warp_max(m2); m3 = warp_max(m3);

    // pass 2: exp + denom + weighted gather-sum (all lanes cooperate per edge)
    int ha = lane >> 4;                 // head of float4 #lane (0 or 1)
    float m_a = ha ? m1 : m0;
    float m_b = ha ? m3 : m2;
    float ad_a = ha ? ad.y : ad.x;
    float ad_b = ha ? ad.w : ad.z;
    float den_a = 0.f, den_b = 0.f;
    float4 acc_a = make_float4(0.f, 0.f, 0.f, 0.f);
    float4 acc_b = make_float4(0.f, 0.f, 0.f, 0.f);
    for (int i = beg; i < end; i++) {
        int s = g_csr_src[i];           // uniform across warp
        float4 as = *(const float4*)&g_as1[s * 4];
        float p_a = __expf(lrelu((ha ? as.y : as.x) + ad_a) - m_a);
        float p_b = __expf(lrelu((ha ? as.w : as.z) + ad_b) - m_b);
        den_a += p_a; den_b += p_b;
        const float4* hr = (const float4*)&g_h1[(size_t)s * HH];
        float4 va = hr[lane];
        float4 vb = hr[lane + 32];
        acc_a.x += p_a * va.x; acc_a.y += p_a * va.y;
        acc_a.z += p_a * va.z; acc_a.w += p_a * va.w;
        acc_b.x += p_b * vb.x; acc_b.y += p_b * vb.y;
        acc_b.z += p_b * vb.z; acc_b.w += p_b * vb.w;
    }
    float ia = 1.f / (den_a + 1e-16f);
    float ib = 1.f / (den_b + 1e-16f);
    const float4* bb = (const float4*)b1;
    float4 b_a = bb[lane], b_b = bb[lane + 32];
    float4 oa, ob;
    oa.x = acc_a.x * ia + b_a.x; oa.y = acc_a.y * ia + b_a.y;
    oa.z = acc_a.z * ia + b_a.z; oa.w = acc_a.w * ia + b_a.w;
    ob.x = acc_b.x * ib + b_b.x; ob.y = acc_b.y * ib + b_b.y;
    ob.z = acc_b.z * ib + b_b.z; ob.w = acc_b.w * ib + b_b.w;
    // ELU
    oa.x = oa.x > 0.f ? oa.x : (__expf(oa.x) - 1.f);
    oa.y = oa.y > 0.f ? oa.y : (__expf(oa.y) - 1.f);
    oa.z = oa.z > 0.f ? oa.z : (__expf(oa.z) - 1.f);
    oa.w = oa.w > 0.f ? oa.w : (__expf(oa.w) - 1.f);
    ob.x = ob.x > 0.f ? ob.x : (__expf(ob.x) - 1.f);
    ob.y = ob.y > 0.f ? ob.y : (__expf(ob.y) - 1.f);
    ob.z = ob.z > 0.f ? ob.z : (__expf(ob.z) - 1.f);
    ob.w = ob.w > 0.f ? ob.w : (__expf(ob.w) - 1.f);
    float4* og = (float4*)&g_agg1[(size_t)node * HH];
    og[lane] = oa;
    og[lane + 32] = ob;
}

// ================= fused layer2: softmax + aggregate + bias + L2 normalize =================
__global__ __launch_bounds__(256) void agg2_kernel(
    float* __restrict__ out, const float* __restrict__ b2)
{
    int node = blockIdx.x * 8 + (threadIdx.x >> 5);
    int lane = threadIdx.x & 31;
    if (node >= NN) return;
    int beg = g_off[node], end = g_off[node + 1];

    float ad = g_ad2[node];

    float m = -1e30f;
    for (int i = beg + lane; i < end; i += 32) {
        int s = g_csr_src[i];
        m = fmaxf(m, lrelu(g_as2[s] + ad));
    }
    m = warp_max(m);

    float den = 0.f;
    float4 acc = make_float4(0.f, 0.f, 0.f, 0.f);
    for (int i = beg; i < end; i++) {
        int s = g_csr_src[i];
        float p = __expf(lrelu(g_as2[s] + ad) - m);
        den += p;
        float4 v = ((const float4*)&g_h2p[(size_t)s * ODIM])[lane];
        acc.x += p * v.x; acc.y += p * v.y; acc.z += p * v.z; acc.w += p * v.w;
    }
    float iv = 1.f / (den + 1e-16f);
    float4 b = ((const float4*)b2)[lane];
    float4 v;
    v.x = acc.x * iv + b.x; v.y = acc.y * iv + b.y;
    v.z = acc.z * iv + b.z; v.w = acc.w * iv + b.w;
    float ss = warp_sum(v.x * v.x + v.y * v.y + v.z * v.z + v.w * v.w);
    float sc = 1.f / fmaxf(sqrtf(ss), 1e-12f);
    v.x *= sc; v.y *= sc; v.z *= sc; v.w *= sc;
    ((float4*)(out + (size_t)node * ODIM))[lane] = v;
}

// ================= host =================
extern "C" void kernel_launch(void* const* d_in, const int* in_sizes, int n_in,
                              void* d_out, int out_size)
{
    const float* x      = (const float*)d_in[0];
    const int*   ei     = (const int*)d_in[1];     // int32 (JAX x64 disabled)
    const float* W1     = (const float*)d_in[2];
    const float* a_src1 = (const float*)d_in[3];
    const float* a_dst1 = (const float*)d_in[4];
    const float* b1     = (const float*)d_in[5];
    const float* W2     = (const float*)d_in[6];
    const float* a_src2 = (const float*)d_in[7];
    const float* a_dst2 = (const float*)d_in[8];
    const float* b2     = (const float*)d_in[9];
    float*       out    = (float*)d_out;
    const int*   srcp   = ei;
    const int*   dstp   = ei + NE;

    void* p_deg;
    cudaGetSymbolAddress(&p_deg, g_deg);
    void *p_h1, *p_agg1, *p_h2p;
    cudaGetSymbolAddress(&p_h1,   g_h1);
    cudaGetSymbolAddress(&p_agg1, g_agg1);
    cudaGetSymbolAddress(&p_h2p,  g_h2p);

    cudaStream_t st = 0;
    const int EB = (TE + 255) / 256;

    // ---- CSR build (by dst) ----
    cudaMemsetAsync(p_deg, 0, sizeof(int) * NN, st);
    hist_kernel<<<EB, 256, 0, st>>>(srcp, dstp);
    scan_kernel<<<1, 1024, 0, st>>>();
    scatter_kernel<<<EB, 256, 0, st>>>(srcp, dstp);

    // ---- layer 1 ----
    gemm_kernel<<<dim3(782, 4), 256, 0, st>>>(x, W1, (float*)p_h1, NN, IN_DIM, HH);
    alpha1_kernel<<<(NN * 32 + 255) / 256, 256, 0, st>>>(a_src1, a_dst1);
    agg1_kernel<<<(NN + 7) / 8, 256, 0, st>>>(b1);

    // ---- layer 2 ----
    gemm_kernel<<<dim3(782, 2), 256, 0, st>>>((const float*)p_agg1, W2,
                                              (float*)p_h2p, NN, HH, ODIM);
    alpha2_kernel<<<(NN * 32 + 255) / 256, 256, 0, st>>>(a_src2, a_dst2);
    agg2_kernel<<<(NN + 7) / 8, 256, 0, st>>>(out, b2);
}

// round 9
// speedup vs baseline: 1.5676x; 1.0967x over previous
#include <cuda_runtime.h>
#include <math.h>

#define NN 50000
#define NE 800000
#define TE (NE + NN)          // edges + self loops
#define IN_DIM 128
#define HH 256                // HEADS*HID
#define ODIM 128
#define NEG_SLOPE 0.2f

// ---------------- scratch (device globals; no allocs allowed) ----------------
__device__ __align__(16) float g_h1[(size_t)NN * HH];     // layer1 projection
__device__ __align__(16) float g_agg1[(size_t)NN * HH];   // layer1 out (post ELU) = layer2 in
__device__ __align__(16) float g_h2p[(size_t)NN * ODIM];  // layer2 projection
__device__ __align__(16) float g_as1[NN * 4];
__device__ __align__(16) float g_ad1[NN * 4];
__device__ __align__(16) float g_as2[NN];
__device__ __align__(16) float g_ad2[NN];
// CSR (by destination node)
__device__ int g_deg[NN];
__device__ int g_off[NN + 1];
__device__ int g_cur[NN];
__device__ int g_csr_src[TE];

// ---------------- helpers ----------------
__device__ __forceinline__ float warp_sum(float v) {
    #pragma unroll
    for (int off = 16; off; off >>= 1) v += __shfl_xor_sync(0xffffffffu, v, off);
    return v;
}
__device__ __forceinline__ float warp_max(float v) {
    #pragma unroll
    for (int off = 16; off; off >>= 1) v = fmaxf(v, __shfl_xor_sync(0xffffffffu, v, off));
    return v;
}
__device__ __forceinline__ float lrelu(float v) {
    return v > 0.f ? v : NEG_SLOPE * v;
}
__device__ __forceinline__ bool edge_sd(int e, const int* __restrict__ src,
                                        const int* __restrict__ dst, int& s, int& d) {
    if (e < NE) { s = src[e]; d = dst[e]; } else { s = d = e - NE; }
    return ((unsigned)s < (unsigned)NN) && ((unsigned)d < (unsigned)NN);
}

// ================= CSR build =================
__global__ __launch_bounds__(256) void hist_kernel(
    const int* __restrict__ src, const int* __restrict__ dst)
{
    int e = blockIdx.x * blockDim.x + threadIdx.x;
    if (e >= TE) return;
    int s, d;
    if (!edge_sd(e, src, dst, s, d)) return;
    atomicAdd(&g_deg[d], 1);
}

// single-block scan: each thread owns a contiguous chunk, one block-scan of totals
#define SCAN_T 1024
#define CHUNK ((NN + SCAN_T - 1) / SCAN_T)     // 49
__global__ __launch_bounds__(SCAN_T) void scan_kernel()
{
    __shared__ int warp_tot[32];
    int tid = threadIdx.x;
    int lane = tid & 31;
    int wid = tid >> 5;
    int t0 = tid * CHUNK;

    int local[CHUNK];
    int sum = 0;
    #pragma unroll
    for (int i = 0; i < CHUNK; i++) {
        int idx = t0 + i;
        int v = (idx < NN) ? g_deg[idx] : 0;
        local[i] = v;
        sum += v;
    }
    // warp inclusive scan of sum
    int incl = sum;
    #pragma unroll
    for (int off = 1; off < 32; off <<= 1) {
        int t = __shfl_up_sync(0xffffffffu, incl, off);
        if (lane >= off) incl += t;
    }
    if (lane == 31) warp_tot[wid] = incl;
    __syncthreads();
    if (wid == 0) {
        int w = warp_tot[lane];
        #pragma unroll
        for (int off = 1; off < 32; off <<= 1) {
            int t = __shfl_up_sync(0xffffffffu, w, off);
            if (lane >= off) w += t;
        }
        warp_tot[lane] = w;
    }
    __syncthreads();
    int pre = incl - sum + (wid ? warp_tot[wid - 1] : 0);   // exclusive prefix
    #pragma unroll
    for (int i = 0; i < CHUNK; i++) {
        int idx = t0 + i;
        if (idx < NN) { g_off[idx] = pre; g_cur[idx] = pre; }
        pre += local[i];
    }
    if (tid == SCAN_T - 1) g_off[NN] = pre;
}

__global__ __launch_bounds__(256) void scatter_kernel(
    const int* __restrict__ src, const int* __restrict__ dst)
{
    int e = blockIdx.x * blockDim.x + threadIdx.x;
    if (e >= TE) return;
    int s, d;
    if (!edge_sd(e, src, dst, s, d)) return;
    int pos = atomicAdd(&g_cur[d], 1);
    g_csr_src[pos] = s;
}

// ================= GEMM: C[n,M] = A[n,K] @ B[K,M] =================
// 128x128 tile, BK=8, 256 threads, 8x8 register blocking, reg-prefetch pipeline.
#define BM 128
#define BN 128
#define BK 8
__global__ __launch_bounds__(256) void gemm_kernel(
    const float* __restrict__ A, const float* __restrict__ B,
    float* __restrict__ C, int n, int K, int M)
{
    __shared__ float sA[BK][BM + 4];
    __shared__ float sB[BK][BN];
    int tid = threadIdx.x;
    int row0 = blockIdx.x * BM;
    int col0 = blockIdx.y * BN;

    // A tile loader: 128 rows x 8 k = 1024 floats = 256 x float4
    int a_row = tid >> 1;
    int a_k4  = (tid & 1) * 4;
    bool a_ok = (row0 + a_row) < n;
    const float* Aptr = A + (size_t)(row0 + a_row) * K + a_k4;
    // B tile loader: 8 k x 128 cols
    int b_kk = tid >> 5;
    int b_c4 = (tid & 31) * 4;
    const float* Bptr = B + (size_t)b_kk * M + col0 + b_c4;

    int tr = (tid >> 4) * 8;   // row offset of this thread's 8x8 tile
    int tc = (tid & 15) * 8;   // col offset

    float acc[8][8];
    #pragma unroll
    for (int i = 0; i < 8; i++)
        #pragma unroll
        for (int j = 0; j < 8; j++) acc[i][j] = 0.f;

    float4 av = a_ok ? *(const float4*)Aptr : make_float4(0.f, 0.f, 0.f, 0.f);
    float4 bv = *(const float4*)Bptr;

    for (int k0 = 0; k0 < K; k0 += BK) {
        sA[a_k4 + 0][a_row] = av.x;
        sA[a_k4 + 1][a_row] = av.y;
        sA[a_k4 + 2][a_row] = av.z;
        sA[a_k4 + 3][a_row] = av.w;
        *(float4*)&sB[b_kk][b_c4] = bv;
        __syncthreads();

        if (k0 + BK < K) {
            av = a_ok ? *(const float4*)(Aptr + k0 + BK) : make_float4(0.f, 0.f, 0.f, 0.f);
            bv = *(const float4*)(Bptr + (size_t)(k0 + BK) * M);
        }

        #pragma unroll
        for (int kk = 0; kk < BK; kk++) {
            float4 a0 = *(const float4*)&sA[kk][tr];
            float4 a1 = *(const float4*)&sA[kk][tr + 4];
            float4 b0 = *(const float4*)&sB[kk][tc];
            float4 b1 = *(const float4*)&sB[kk][tc + 4];
            float ar[8] = {a0.x, a0.y, a0.z, a0.w, a1.x, a1.y, a1.z, a1.w};
            float br[8] = {b0.x, b0.y, b0.z, b0.w, b1.x, b1.y, b1.z, b1.w};
            #pragma unroll
            for (int i = 0; i < 8; i++)
                #pragma unroll
                for (int j = 0; j < 8; j++)
                    acc[i][j] += ar[i] * br[j];
        }
        __syncthreads();
    }

    #pragma unroll
    for (int i = 0; i < 8; i++) {
        int row = row0 + tr + i;
        if (row < n) {
            float* cp = C + (size_t)row * M + col0 + tc;
            *(float4*)cp       = make_float4(acc[i][0], acc[i][1], acc[i][2], acc[i][3]);
            *(float4*)(cp + 4) = make_float4(acc[i][4], acc[i][5], acc[i][6], acc[i][7]);
        }
    }
}

// ================= per-node attention scalars =================
__global__ __launch_bounds__(256) void alpha1_kernel(
    const float* __restrict__ a_src, const float* __restrict__ a_dst)
{
    int node = (blockIdx.x * blockDim.x + threadIdx.x) >> 5;
    int lane = threadIdx.x & 31;
    if (node >= NN) return;
    const float* h = &g_h1[(size_t)node * HH];
    float s[4] = {0, 0, 0, 0}, d[4] = {0, 0, 0, 0};
    #pragma unroll
    for (int k = 0; k < 8; k++) {
        int c = lane + 32 * k;
        float hv = h[c];
        s[k >> 1] += hv * a_src[c];
        d[k >> 1] += hv * a_dst[c];
    }
    #pragma unroll
    for (int hh = 0; hh < 4; hh++) { s[hh] = warp_sum(s[hh]); d[hh] = warp_sum(d[hh]); }
    if (lane == 0) {
        #pragma unroll
        for (int hh = 0; hh < 4; hh++) {
            g_as1[node * 4 + hh] = s[hh];
            g_ad1[node * 4 + hh] = d[hh];
        }
    }
}

__global__ __launch_bounds__(256) void alpha2_kernel(
    const float* __restrict__ a_src, const float* __restrict__ a_dst)
{
    int node = (blockIdx.x * blockDim.x + threadIdx.x) >> 5;
    int lane = threadIdx.x & 31;
    if (node >= NN) return;
    const float* h = &g_h2p[(size_t)node * ODIM];
    float s = 0.f, d = 0.f;
    #pragma unroll
    for (int k = 0; k < 4; k++) {
        int c = lane + 32 * k;
        float hv = h[c];
        s += hv * a_src[c];
        d += hv * a_dst[c];
    }
    s = warp_sum(s); d = warp_sum(d);
    if (lane == 0) { g_as2[node] = s; g_ad2[node] = d; }
}

// ================= fused layer1: softmax + aggregate + bias + ELU =================
__global__ __launch_bounds__(256) void agg1_kernel(const float* __restrict__ b1)
{
    int node = blockIdx.x * 8 + (threadIdx.x >> 5);
    int lane = threadIdx.x & 31;
    if (node >= NN) return;
    int beg = g_off[node], end = g_off[node + 1];

    float4 ad = *(const float4*)&g_ad1[node * 4];

    float m0 = -1e30f, m1 = -1e30f, m2 = -1e30f, m3 = -1e30f;
    for (int i = beg + lane; i < end; i += 32) {
        int s = g_csr_src[i];
        float4 as = *(const float4*)&g_as1[s * 4];
        m0 = fmaxf(m0, lrelu(as.x + ad.x));
        m1 = fmaxf(m1, lrelu(as.y + ad.y));
        m2 = fmaxf(m2, lrelu(as.z + ad.z));
        m3 = fmaxf(m3, lrelu(as.w + ad.w));
    }
    m0 = warp_max(m0); m1 = warp_max(m1); m2 = warp_max(m2); m3 = warp_max(m3);

    int ha = lane >> 4;
    float m_a = ha ? m1 : m0;
    float m_b = ha ? m3 : m2;
    float ad_a = ha ? ad.y : ad.x;
    float ad_b = ha ? ad.w : ad.z;
    float den_a = 0.f, den_b = 0.f;
    float4 acc_a = make_float4(0.f, 0.f, 0.f, 0.f);
    float4 acc_b = make_float4(0.f, 0.f, 0.f, 0.f);
    for (int i = beg; i < end; i++) {
        int s = g_csr_src[i];
        float4 as = *(const float4*)&g_as1[s * 4];
        float p_a = __expf(lrelu((ha ? as.y : as.x) + ad_a) - m_a);
        float p_b = __expf(lrelu((ha ? as.w : as.z) + ad_b) - m_b);
        den_a += p_a; den_b += p_b;
        const float4* hr = (const float4*)&g_h1[(size_t)s * HH];
        float4 va = hr[lane];
        float4 vb = hr[lane + 32];
        acc_a.x += p_a * va.x; acc_a.y += p_a * va.y;
        acc_a.z += p_a * va.z; acc_a.w += p_a * va.w;
        acc_b.x += p_b * vb.x; acc_b.y += p_b * vb.y;
        acc_b.z += p_b * vb.z; acc_b.w += p_b * vb.w;
    }
    float ia = 1.f / (den_a + 1e-16f);
    float ib = 1.f / (den_b + 1e-16f);
    const float4* bb = (const float4*)b1;
    float4 b_a = bb[lane], b_b = bb[lane + 32];
    float4 oa, ob;
    oa.x = acc_a.x * ia + b_a.x; oa.y = acc_a.y * ia + b_a.y;
    oa.z = acc_a.z * ia + b_a.z; oa.w = acc_a.w * ia + b_a.w;
    ob.x = acc_b.x * ib + b_b.x; ob.y = acc_b.y * ib + b_b.y;
    ob.z = acc_b.z * ib + b_b.z; ob.w = acc_b.w * ib + b_b.w;
    oa.x = oa.x > 0.f ? oa.x : (__expf(oa.x) - 1.f);
    oa.y = oa.y > 0.f ? oa.y : (__expf(oa.y) - 1.f);
    oa.z = oa.z > 0.f ? oa.z : (__expf(oa.z) - 1.f);
    oa.w = oa.w > 0.f ? oa.w : (__expf(oa.w) - 1.f);
    ob.x = ob.x > 0.f ? ob.x : (__expf(ob.x) - 1.f);
    ob.y = ob.y > 0.f ? ob.y : (__expf(ob.y) - 1.f);
    ob.z = ob.z > 0.f ? ob.z : (__expf(ob.z) - 1.f);
    ob.w = ob.w > 0.f ? ob.w : (__expf(ob.w) - 1.f);
    float4* og = (float4*)&g_agg1[(size_t)node * HH];
    og[lane] = oa;
    og[lane + 32] = ob;
}

// ================= fused layer2: softmax + aggregate + bias + L2 normalize ======
__global__ __launch_bounds__(256) void agg2_kernel(
    float* __restrict__ out, const float* __restrict__ b2)
{
    int node = blockIdx.x * 8 + (threadIdx.x >> 5);
    int lane = threadIdx.x & 31;
    if (node >= NN) return;
    int beg = g_off[node], end = g_off[node + 1];

    float ad = g_ad2[node];

    float m = -1e30f;
    for (int i = beg + lane; i < end; i += 32) {
        int s = g_csr_src[i];
        m = fmaxf(m, lrelu(g_as2[s] + ad));
    }
    m = warp_max(m);

    float den = 0.f;
    float4 acc = make_float4(0.f, 0.f, 0.f, 0.f);
    for (int i = beg; i < end; i++) {
        int s = g_csr_src[i];
        float p = __expf(lrelu(g_as2[s] + ad) - m);
        den += p;
        float4 v = ((const float4*)&g_h2p[(size_t)s * ODIM])[lane];
        acc.x += p * v.x; acc.y += p * v.y; acc.z += p * v.z; acc.w += p * v.w;
    }
    float iv = 1.f / (den + 1e-16f);
    float4 b = ((const float4*)b2)[lane];
    float4 v;
    v.x = acc.x * iv + b.x; v.y = acc.y * iv + b.y;
    v.z = acc.z * iv + b.z; v.w = acc.w * iv + b.w;
    float ss = warp_sum(v.x * v.x + v.y * v.y + v.z * v.z + v.w * v.w);
    float sc = 1.f / fmaxf(sqrtf(ss), 1e-12f);
    v.x *= sc; v.y *= sc; v.z *= sc; v.w *= sc;
    ((float4*)(out + (size_t)node * ODIM))[lane] = v;
}

// ================= host =================
extern "C" void kernel_launch(void* const* d_in, const int* in_sizes, int n_in,
                              void* d_out, int out_size)
{
    const float* x      = (const float*)d_in[0];
    const int*   ei     = (const int*)d_in[1];     // int32 (JAX x64 disabled)
    const float* W1     = (const float*)d_in[2];
    const float* a_src1 = (const float*)d_in[3];
    const float* a_dst1 = (const float*)d_in[4];
    const float* b1     = (const float*)d_in[5];
    const float* W2     = (const float*)d_in[6];
    const float* a_src2 = (const float*)d_in[7];
    const float* a_dst2 = (const float*)d_in[8];
    const float* b2     = (const float*)d_in[9];
    float*       out    = (float*)d_out;
    const int*   srcp   = ei;
    const int*   dstp   = ei + NE;

    void* p_deg;
    cudaGetSymbolAddress(&p_deg, g_deg);
    void *p_h1, *p_agg1, *p_h2p;
    cudaGetSymbolAddress(&p_h1,   g_h1);
    cudaGetSymbolAddress(&p_agg1, g_agg1);
    cudaGetSymbolAddress(&p_h2p,  g_h2p);

    cudaStream_t st = 0;
    const int EB = (TE + 255) / 256;
    const int MBLK = (NN + BM - 1) / BM;   // 391

    // ---- CSR build (by dst) ----
    cudaMemsetAsync(p_deg, 0, sizeof(int) * NN, st);
    hist_kernel<<<EB, 256, 0, st>>>(srcp, dstp);
    scan_kernel<<<1, SCAN_T, 0, st>>>();
    scatter_kernel<<<EB, 256, 0, st>>>(srcp, dstp);

    // ---- layer 1 ----
    gemm_kernel<<<dim3(MBLK, 2), 256, 0, st>>>(x, W1, (float*)p_h1, NN, IN_DIM, HH);
    alpha1_kernel<<<(NN * 32 + 255) / 256, 256, 0, st>>>(a_src1, a_dst1);
    agg1_kernel<<<(NN + 7) / 8, 256, 0, st>>>(b1);

    // ---- layer 2 ----
    gemm_kernel<<<dim3(MBLK, 1), 256, 0, st>>>((const float*)p_agg1, W2,
                                               (float*)p_h2p, NN, HH, ODIM);
    alpha2_kernel<<<(NN * 32 + 255) / 256, 256, 0, st>>>(a_src2, a_dst2);
    agg2_kernel<<<(NN + 7) / 8, 256, 0, st>>>(out, b2);
}

// round 10
// speedup vs baseline: 2.1929x; 1.3989x over previous
#include <cuda_runtime.h>
#include <math.h>

#define NN 50000
#define NE 800000
#define TE (NE + NN)          // edges + self loops
#define IN_DIM 128
#define HH 256                // HEADS*HID
#define ODIM 128
#define NEG_SLOPE 0.2f

// ---------------- scratch (device globals; no allocs allowed) ----------------
__device__ __align__(16) float g_h1[(size_t)NN * HH];     // layer1 projection
__device__ __align__(16) float g_agg1[(size_t)NN * HH];   // layer1 out (post ELU) = layer2 in
__device__ __align__(16) float g_h2p[(size_t)NN * ODIM];  // layer2 projection
__device__ __align__(16) float g_as1[NN * 4];
__device__ __align__(16) float g_ad1[NN * 4];
__device__ __align__(16) float g_as2[NN];
__device__ __align__(16) float g_ad2[NN];
// CSR (by destination node)
__device__ int g_deg[NN];
__device__ int g_off[NN + 1];
__device__ int g_cur[NN];
__device__ int g_csr_src[TE];

// ---------------- helpers ----------------
__device__ __forceinline__ float warp_sum(float v) {
    #pragma unroll
    for (int off = 16; off; off >>= 1) v += __shfl_xor_sync(0xffffffffu, v, off);
    return v;
}
__device__ __forceinline__ float warp_max(float v) {
    #pragma unroll
    for (int off = 16; off; off >>= 1) v = fmaxf(v, __shfl_xor_sync(0xffffffffu, v, off));
    return v;
}
__device__ __forceinline__ float lrelu(float v) {
    return v > 0.f ? v : NEG_SLOPE * v;
}
__device__ __forceinline__ bool edge_sd(int e, const int* __restrict__ src,
                                        const int* __restrict__ dst, int& s, int& d) {
    if (e < NE) { s = src[e]; d = dst[e]; } else { s = d = e - NE; }
    return ((unsigned)s < (unsigned)NN) && ((unsigned)d < (unsigned)NN);
}
__device__ __forceinline__ unsigned f2tf32(float f) {
    unsigned u;
    asm("cvt.rna.tf32.f32 %0, %1;" : "=r"(u) : "f"(f));
    return u;
}

// ================= CSR build =================
__global__ __launch_bounds__(256) void hist_kernel(
    const int* __restrict__ src, const int* __restrict__ dst)
{
    int e = blockIdx.x * blockDim.x + threadIdx.x;
    if (e >= TE) return;
    int s, d;
    if (!edge_sd(e, src, dst, s, d)) return;
    atomicAdd(&g_deg[d], 1);
}

#define SCAN_T 1024
#define CHUNK ((NN + SCAN_T - 1) / SCAN_T)     // 49
__global__ __launch_bounds__(SCAN_T) void scan_kernel()
{
    __shared__ int warp_tot[32];
    int tid = threadIdx.x;
    int lane = tid & 31;
    int wid = tid >> 5;
    int t0 = tid * CHUNK;

    int local[CHUNK];
    int sum = 0;
    #pragma unroll
    for (int i = 0; i < CHUNK; i++) {
        int idx = t0 + i;
        int v = (idx < NN) ? g_deg[idx] : 0;
        local[i] = v;
        sum += v;
    }
    int incl = sum;
    #pragma unroll
    for (int off = 1; off < 32; off <<= 1) {
        int t = __shfl_up_sync(0xffffffffu, incl, off);
        if (lane >= off) incl += t;
    }
    if (lane == 31) warp_tot[wid] = incl;
    __syncthreads();
    if (wid == 0) {
        int w = warp_tot[lane];
        #pragma unroll
        for (int off = 1; off < 32; off <<= 1) {
            int t = __shfl_up_sync(0xffffffffu, w, off);
            if (lane >= off) w += t;
        }
        warp_tot[lane] = w;
    }
    __syncthreads();
    int pre = incl - sum + (wid ? warp_tot[wid - 1] : 0);
    #pragma unroll
    for (int i = 0; i < CHUNK; i++) {
        int idx = t0 + i;
        if (idx < NN) { g_off[idx] = pre; g_cur[idx] = pre; }
        pre += local[i];
    }
    if (tid == SCAN_T - 1) g_off[NN] = pre;
}

__global__ __launch_bounds__(256) void scatter_kernel(
    const int* __restrict__ src, const int* __restrict__ dst)
{
    int e = blockIdx.x * blockDim.x + threadIdx.x;
    if (e >= TE) return;
    int s, d;
    if (!edge_sd(e, src, dst, s, d)) return;
    int pos = atomicAdd(&g_cur[d], 1);
    g_csr_src[pos] = s;
}

// ================= tf32 tensor-core GEMM: C[n,M] = A[n,K] @ B[K,M] =================
// 128x128x16 tile, 256 threads (8 warps, 2x4), each warp 64x32 via m16n8k8 mma.
#define BM 128
#define BN 128
#define BKT 16
#define SPAD 4
__global__ __launch_bounds__(256) void gemm_tf32_kernel(
    const float* __restrict__ A, const float* __restrict__ B,
    float* __restrict__ C, int n, int K, int M)
{
    __shared__ unsigned sA[BKT][BM + SPAD];   // [k][row] tf32 bits
    __shared__ unsigned sB[BKT][BN + SPAD];   // [k][col] tf32 bits
    int tid = threadIdx.x;
    int lane = tid & 31, wid = tid >> 5;
    int warp_m = (wid >> 2) * 64;   // 0 or 64
    int warp_n = (wid & 3) * 32;    // 0,32,64,96
    int row0 = blockIdx.x * BM, col0 = blockIdx.y * BN;
    int gid = lane >> 2;            // groupID 0..7
    int tig = lane & 3;             // threadID in group 0..3

    float acc[4][4][4];             // [mi][ni][c0..c3]
    #pragma unroll
    for (int mi = 0; mi < 4; mi++)
        #pragma unroll
        for (int ni = 0; ni < 4; ni++)
            #pragma unroll
            for (int c = 0; c < 4; c++) acc[mi][ni][c] = 0.f;

    for (int k0 = 0; k0 < K; k0 += BKT) {
        // load A tile: 128 rows x 16 k, transposed store into sA[k][row]
        #pragma unroll
        for (int t = 0; t < 2; t++) {
            int i = tid + t * 256;           // float4 index 0..511
            int row = i >> 2;
            int cb = (i & 3) * 4;
            float4 v = make_float4(0.f, 0.f, 0.f, 0.f);
            if (row0 + row < n)
                v = *(const float4*)(A + (size_t)(row0 + row) * K + k0 + cb);
            sA[cb + 0][row] = f2tf32(v.x);
            sA[cb + 1][row] = f2tf32(v.y);
            sA[cb + 2][row] = f2tf32(v.z);
            sA[cb + 3][row] = f2tf32(v.w);
        }
        // load B tile: 16 k x 128 cols
        #pragma unroll
        for (int t = 0; t < 2; t++) {
            int i = tid + t * 256;
            int kk = i >> 5;
            int cb = (i & 31) * 4;
            float4 v = *(const float4*)(B + (size_t)(k0 + kk) * M + col0 + cb);
            sB[kk][cb + 0] = f2tf32(v.x);
            sB[kk][cb + 1] = f2tf32(v.y);
            sB[kk][cb + 2] = f2tf32(v.z);
            sB[kk][cb + 3] = f2tf32(v.w);
        }
        __syncthreads();

        #pragma unroll
        for (int kc = 0; kc < BKT; kc += 8) {
            unsigned af[4][4], bf[4][2];
            #pragma unroll
            for (int mi = 0; mi < 4; mi++) {
                int r = warp_m + mi * 16 + gid;
                int c = kc + tig;
                af[mi][0] = sA[c][r];          // (row g,   col t)
                af[mi][1] = sA[c][r + 8];      // (row g+8, col t)
                af[mi][2] = sA[c + 4][r];      // (row g,   col t+4)
                af[mi][3] = sA[c + 4][r + 8];  // (row g+8, col t+4)
            }
            #pragma unroll
            for (int ni = 0; ni < 4; ni++) {
                int cc = warp_n + ni * 8 + gid;
                int rr = kc + tig;
                bf[ni][0] = sB[rr][cc];        // (k t,   n g)
                bf[ni][1] = sB[rr + 4][cc];    // (k t+4, n g)
            }
            #pragma unroll
            for (int mi = 0; mi < 4; mi++)
                #pragma unroll
                for (int ni = 0; ni < 4; ni++) {
                    asm volatile(
                        "mma.sync.aligned.m16n8k8.row.col.f32.tf32.tf32.f32 "
                        "{%0,%1,%2,%3}, {%4,%5,%6,%7}, {%8,%9}, {%0,%1,%2,%3};"
                        : "+f"(acc[mi][ni][0]), "+f"(acc[mi][ni][1]),
                          "+f"(acc[mi][ni][2]), "+f"(acc[mi][ni][3])
                        : "r"(af[mi][0]), "r"(af[mi][1]), "r"(af[mi][2]), "r"(af[mi][3]),
                          "r"(bf[ni][0]), "r"(bf[ni][1]));
                }
        }
        __syncthreads();
    }

    // epilogue: c0/c1 at (row g, col 2t..2t+1), c2/c3 at (row g+8)
    #pragma unroll
    for (int mi = 0; mi < 4; mi++) {
        int r = row0 + warp_m + mi * 16 + gid;
        #pragma unroll
        for (int ni = 0; ni < 4; ni++) {
            int c = col0 + warp_n + ni * 8 + 2 * tig;
            if (r < n)
                *(float2*)(C + (size_t)r * M + c) =
                    make_float2(acc[mi][ni][0], acc[mi][ni][1]);
            if (r + 8 < n)
                *(float2*)(C + (size_t)(r + 8) * M + c) =
                    make_float2(acc[mi][ni][2], acc[mi][ni][3]);
        }
    }
}

// ================= per-node attention scalars =================
__global__ __launch_bounds__(256) void alpha1_kernel(
    const float* __restrict__ a_src, const float* __restrict__ a_dst)
{
    int node = (blockIdx.x * blockDim.x + threadIdx.x) >> 5;
    int lane = threadIdx.x & 31;
    if (node >= NN) return;
    const float* h = &g_h1[(size_t)node * HH];
    float s[4] = {0, 0, 0, 0}, d[4] = {0, 0, 0, 0};
    #pragma unroll
    for (int k = 0; k < 8; k++) {
        int c = lane + 32 * k;
        float hv = h[c];
        s[k >> 1] += hv * a_src[c];
        d[k >> 1] += hv * a_dst[c];
    }
    #pragma unroll
    for (int hh = 0; hh < 4; hh++) { s[hh] = warp_sum(s[hh]); d[hh] = warp_sum(d[hh]); }
    if (lane == 0) {
        #pragma unroll
        for (int hh = 0; hh < 4; hh++) {
            g_as1[node * 4 + hh] = s[hh];
            g_ad1[node * 4 + hh] = d[hh];
        }
    }
}

__global__ __launch_bounds__(256) void alpha2_kernel(
    const float* __restrict__ a_src, const float* __restrict__ a_dst)
{
    int node = (blockIdx.x * blockDim.x + threadIdx.x) >> 5;
    int lane = threadIdx.x & 31;
    if (node >= NN) return;
    const float* h = &g_h2p[(size_t)node * ODIM];
    float s = 0.f, d = 0.f;
    #pragma unroll
    for (int k = 0; k < 4; k++) {
        int c = lane + 32 * k;
        float hv = h[c];
        s += hv * a_src[c];
        d += hv * a_dst[c];
    }
    s = warp_sum(s); d = warp_sum(d);
    if (lane == 0) { g_as2[node] = s; g_ad2[node] = d; }
}

// ================= fused layer1: softmax + aggregate + bias + ELU =================
__global__ __launch_bounds__(256) void agg1_kernel(const float* __restrict__ b1)
{
    int node = blockIdx.x * 8 + (threadIdx.x >> 5);
    int lane = threadIdx.x & 31;
    if (node >= NN) return;
    int beg = g_off[node], end = g_off[node + 1];

    float4 ad = *(const float4*)&g_ad1[node * 4];

    float m0 = -1e30f, m1 = -1e30f, m2 = -1e30f, m3 = -1e30f;
    for (int i = beg + lane; i < end; i += 32) {
        int s = g_csr_src[i];
        float4 as = *(const float4*)&g_as1[s * 4];
        m0 = fmaxf(m0, lrelu(as.x + ad.x));
        m1 = fmaxf(m1, lrelu(as.y + ad.y));
        m2 = fmaxf(m2, lrelu(as.z + ad.z));
        m3 = fmaxf(m3, lrelu(as.w + ad.w));
    }
    m0 = warp_max(m0); m1 = warp_max(m1); m2 = warp_max(m2); m3 = warp_max(m3);

    int ha = lane >> 4;
    float m_a = ha ? m1 : m0;
    float m_b = ha ? m3 : m2;
    float ad_a = ha ? ad.y : ad.x;
    float ad_b = ha ? ad.w : ad.z;
    float den_a = 0.f, den_b = 0.f;
    float4 acc_a = make_float4(0.f, 0.f, 0.f, 0.f);
    float4 acc_b = make_float4(0.f, 0.f, 0.f, 0.f);
    for (int i = beg; i < end; i++) {
        int s = g_csr_src[i];
        float4 as = *(const float4*)&g_as1[s * 4];
        float p_a = __expf(lrelu((ha ? as.y : as.x) + ad_a) - m_a);
        float p_b = __expf(lrelu((ha ? as.w : as.z) + ad_b) - m_b);
        den_a += p_a; den_b += p_b;
        const float4* hr = (const float4*)&g_h1[(size_t)s * HH];
        float4 va = hr[lane];
        float4 vb = hr[lane + 32];
        acc_a.x += p_a * va.x; acc_a.y += p_a * va.y;
        acc_a.z += p_a * va.z; acc_a.w += p_a * va.w;
        acc_b.x += p_b * vb.x; acc_b.y += p_b * vb.y;
        acc_b.z += p_b * vb.z; acc_b.w += p_b * vb.w;
    }
    float ia = 1.f / (den_a + 1e-16f);
    float ib = 1.f / (den_b + 1e-16f);
    const float4* bb = (const float4*)b1;
    float4 b_a = bb[lane], b_b = bb[lane + 32];
    float4 oa, ob;
    oa.x = acc_a.x * ia + b_a.x; oa.y = acc_a.y * ia + b_a.y;
    oa.z = acc_a.z * ia + b_a.z; oa.w = acc_a.w * ia + b_a.w;
    ob.x = acc_b.x * ib + b_b.x; ob.y = acc_b.y * ib + b_b.y;
    ob.z = acc_b.z * ib + b_b.z; ob.w = acc_b.w * ib + b_b.w;
    oa.x = oa.x > 0.f ? oa.x : (__expf(oa.x) - 1.f);
    oa.y = oa.y > 0.f ? oa.y : (__expf(oa.y) - 1.f);
    oa.z = oa.z > 0.f ? oa.z : (__expf(oa.z) - 1.f);
    oa.w = oa.w > 0.f ? oa.w : (__expf(oa.w) - 1.f);
    ob.x = ob.x > 0.f ? ob.x : (__expf(ob.x) - 1.f);
    ob.y = ob.y > 0.f ? ob.y : (__expf(ob.y) - 1.f);
    ob.z = ob.z > 0.f ? ob.z : (__expf(ob.z) - 1.f);
    ob.w = ob.w > 0.f ? ob.w : (__expf(ob.w) - 1.f);
    float4* og = (float4*)&g_agg1[(size_t)node * HH];
    og[lane] = oa;
    og[lane + 32] = ob;
}

// ================= fused layer2: softmax + aggregate + bias + L2 normalize ======
__global__ __launch_bounds__(256) void agg2_kernel(
    float* __restrict__ out, const float* __restrict__ b2)
{
    int node = blockIdx.x * 8 + (threadIdx.x >> 5);
    int lane = threadIdx.x & 31;
    if (node >= NN) return;
    int beg = g_off[node], end = g_off[node + 1];

    float ad = g_ad2[node];

    float m = -1e30f;
    for (int i = beg + lane; i < end; i += 32) {
        int s = g_csr_src[i];
        m = fmaxf(m, lrelu(g_as2[s] + ad));
    }
    m = warp_max(m);

    float den = 0.f;
    float4 acc = make_float4(0.f, 0.f, 0.f, 0.f);
    for (int i = beg; i < end; i++) {
        int s = g_csr_src[i];
        float p = __expf(lrelu(g_as2[s] + ad) - m);
        den += p;
        float4 v = ((const float4*)&g_h2p[(size_t)s * ODIM])[lane];
        acc.x += p * v.x; acc.y += p * v.y; acc.z += p * v.z; acc.w += p * v.w;
    }
    float iv = 1.f / (den + 1e-16f);
    float4 b = ((const float4*)b2)[lane];
    float4 v;
    v.x = acc.x * iv + b.x; v.y = acc.y * iv + b.y;
    v.z = acc.z * iv + b.z; v.w = acc.w * iv + b.w;
    float ss = warp_sum(v.x * v.x + v.y * v.y + v.z * v.z + v.w * v.w);
    float sc = 1.f / fmaxf(sqrtf(ss), 1e-12f);
    v.x *= sc; v.y *= sc; v.z *= sc; v.w *= sc;
    ((float4*)(out + (size_t)node * ODIM))[lane] = v;
}

// ================= host =================
extern "C" void kernel_launch(void* const* d_in, const int* in_sizes, int n_in,
                              void* d_out, int out_size)
{
    const float* x      = (const float*)d_in[0];
    const int*   ei     = (const int*)d_in[1];     // int32 (JAX x64 disabled)
    const float* W1     = (const float*)d_in[2];
    const float* a_src1 = (const float*)d_in[3];
    const float* a_dst1 = (const float*)d_in[4];
    const float* b1     = (const float*)d_in[5];
    const float* W2     = (const float*)d_in[6];
    const float* a_src2 = (const float*)d_in[7];
    const float* a_dst2 = (const float*)d_in[8];
    const float* b2     = (const float*)d_in[9];
    float*       out    = (float*)d_out;
    const int*   srcp   = ei;
    const int*   dstp   = ei + NE;

    void* p_deg;
    cudaGetSymbolAddress(&p_deg, g_deg);
    void *p_h1, *p_agg1, *p_h2p;
    cudaGetSymbolAddress(&p_h1,   g_h1);
    cudaGetSymbolAddress(&p_agg1, g_agg1);
    cudaGetSymbolAddress(&p_h2p,  g_h2p);

    cudaStream_t st = 0;
    const int EB = (TE + 255) / 256;
    const int MBLK = (NN + BM - 1) / BM;   // 391

    // ---- CSR build (by dst) ----
    cudaMemsetAsync(p_deg, 0, sizeof(int) * NN, st);
    hist_kernel<<<EB, 256, 0, st>>>(srcp, dstp);
    scan_kernel<<<1, SCAN_T, 0, st>>>();
    scatter_kernel<<<EB, 256, 0, st>>>(srcp, dstp);

    // ---- layer 1 ----
    gemm_tf32_kernel<<<dim3(MBLK, 2), 256, 0, st>>>(x, W1, (float*)p_h1, NN, IN_DIM, HH);
    alpha1_kernel<<<(NN * 32 + 255) / 256, 256, 0, st>>>(a_src1, a_dst1);
    agg1_kernel<<<(NN + 7) / 8, 256, 0, st>>>(b1);

    // ---- layer 2 ----
    gemm_tf32_kernel<<<dim3(MBLK, 1), 256, 0, st>>>((const float*)p_agg1, W2,
                                                    (float*)p_h2p, NN, HH, ODIM);
    alpha2_kernel<<<(NN * 32 + 255) / 256, 256, 0, st>>>(a_src2, a_dst2);
    agg2_kernel<<<(NN + 7) / 8, 256, 0, st>>>(out, b2);
}

// round 13
// speedup vs baseline: 2.4287x; 1.1075x over previous
#include <cuda_runtime.h>
#include <math.h>

#define NN 50000
#define NE 800000
#define TE (NE + NN)          // edges + self loops
#define IN_DIM 128
#define HH 256                // HEADS*HID
#define ODIM 128
#define NEG_SLOPE 0.2f

// ---------------- scratch (device globals; no allocs allowed) ----------------
__device__ __align__(16) float g_h1[(size_t)NN * HH];     // layer1 projection
__device__ __align__(16) float g_agg1[(size_t)NN * HH];   // layer1 out (post ELU) = layer2 in
__device__ __align__(16) float g_h2p[(size_t)NN * ODIM];  // layer2 projection
__device__ __align__(16) float g_as1[NN * 4];
__device__ __align__(16) float g_ad1[NN * 4];
__device__ __align__(16) float g_as2[NN];
__device__ __align__(16) float g_ad2[NN];
// CSR (by destination node)
__device__ int g_deg[NN];
__device__ int g_off[NN + 1];
__device__ int g_cur[NN];
__device__ int g_csr_src[TE];

// ---------------- helpers ----------------
__device__ __forceinline__ float warp_sum(float v) {
    #pragma unroll
    for (int off = 16; off; off >>= 1) v += __shfl_xor_sync(0xffffffffu, v, off);
    return v;
}
__device__ __forceinline__ float warp_max(float v) {
    #pragma unroll
    for (int off = 16; off; off >>= 1) v = fmaxf(v, __shfl_xor_sync(0xffffffffu, v, off));
    return v;
}
__device__ __forceinline__ float lrelu(float v) {
    return v > 0.f ? v : NEG_SLOPE * v;
}
__device__ __forceinline__ bool edge_sd(int e, const int* __restrict__ src,
                                        const int* __restrict__ dst, int& s, int& d) {
    if (e < NE) { s = src[e]; d = dst[e]; } else { s = d = e - NE; }
    return ((unsigned)s < (unsigned)NN) && ((unsigned)d < (unsigned)NN);
}
__device__ __forceinline__ unsigned f2tf32(float f) {
    unsigned u;
    asm("cvt.rna.tf32.f32 %0, %1;" : "=r"(u) : "f"(f));
    return u;
}
__device__ __forceinline__ void cp16(unsigned dst, const void* src, int src_bytes) {
    asm volatile("cp.async.ca.shared.global [%0], [%1], 16, %2;"
                 :: "r"(dst), "l"(src), "r"(src_bytes));
}
__device__ __forceinline__ void cp_commit() {
    asm volatile("cp.async.commit_group;");
}
__device__ __forceinline__ void cp_wait0() {
    asm volatile("cp.async.wait_group 0;");
}
__device__ __forceinline__ void cp_wait1() {
    asm volatile("cp.async.wait_group 1;");
}

// ================= CSR build =================
__global__ __launch_bounds__(256) void hist_kernel(
    const int* __restrict__ src, const int* __restrict__ dst)
{
    int e = blockIdx.x * blockDim.x + threadIdx.x;
    if (e >= TE) return;
    int s, d;
    if (!edge_sd(e, src, dst, s, d)) return;
    atomicAdd(&g_deg[d], 1);
}

#define SCAN_T 1024
#define CHUNK ((NN + SCAN_T - 1) / SCAN_T)     // 49
__global__ __launch_bounds__(SCAN_T) void scan_kernel()
{
    __shared__ int warp_tot[32];
    int tid = threadIdx.x;
    int lane = tid & 31;
    int wid = tid >> 5;
    int t0 = tid * CHUNK;

    int local[CHUNK];
    int sum = 0;
    #pragma unroll
    for (int i = 0; i < CHUNK; i++) {
        int idx = t0 + i;
        int v = (idx < NN) ? g_deg[idx] : 0;
        local[i] = v;
        sum += v;
    }
    int incl = sum;
    #pragma unroll
    for (int off = 1; off < 32; off <<= 1) {
        int t = __shfl_up_sync(0xffffffffu, incl, off);
        if (lane >= off) incl += t;
    }
    if (lane == 31) warp_tot[wid] = incl;
    __syncthreads();
    if (wid == 0) {
        int w = warp_tot[lane];
        #pragma unroll
        for (int off = 1; off < 32; off <<= 1) {
            int t = __shfl_up_sync(0xffffffffu, w, off);
            if (lane >= off) w += t;
        }
        warp_tot[lane] = w;
    }
    __syncthreads();
    int pre = incl - sum + (wid ? warp_tot[wid - 1] : 0);
    #pragma unroll
    for (int i = 0; i < CHUNK; i++) {
        int idx = t0 + i;
        if (idx < NN) { g_off[idx] = pre; g_cur[idx] = pre; }
        pre += local[i];
    }
    if (tid == SCAN_T - 1) g_off[NN] = pre;
}

__global__ __launch_bounds__(256) void scatter_kernel(
    const int* __restrict__ src, const int* __restrict__ dst)
{
    int e = blockIdx.x * blockDim.x + threadIdx.x;
    if (e >= TE) return;
    int s, d;
    if (!edge_sd(e, src, dst, s, d)) return;
    int pos = atomicAdd(&g_cur[d], 1);
    g_csr_src[pos] = s;
}

// ================= tf32 tensor-core GEMM: C[n,M] = A[n,K] @ B[K,M] =================
// 128x128x16 tile, 256 threads (8 warps, 2x4), each warp 64x32 via m16n8k8 mma.
// cp.async double-buffered; A smem [row][k] pad4, B smem [k][col] pad8 (conflict-free).
#define BM 128
#define BN 128
#define BKT 16
#define APAD 4
#define BPAD 8
#define ASTR (BKT + APAD)     // 20
#define BSTR (BN + BPAD)      // 136
__global__ __launch_bounds__(256) void gemm_tf32_kernel(
    const float* __restrict__ A, const float* __restrict__ B,
    float* __restrict__ C, int n, int K, int M)
{
    __shared__ float sA[2][BM][ASTR];
    __shared__ float sB[2][BKT][BSTR];
    int tid = threadIdx.x;
    int lane = tid & 31, wid = tid >> 5;
    int warp_m = (wid >> 2) * 64;   // 0 or 64
    int warp_n = (wid & 3) * 32;    // 0,32,64,96
    int row0 = blockIdx.x * BM, col0 = blockIdx.y * BN;
    int gid = lane >> 2;            // groupID 0..7
    int tig = lane & 3;             // threadID in group 0..3

    // loader coords (2 x float4 chunks each for A and B)
    int a_row[2], a_cb[2], b_kk[2], b_cb[2];
    const float *a_src[2], *b_src[2];
    unsigned a_dst[2], b_dst[2];
    int a_pred[2];
    unsigned baseA = (unsigned)__cvta_generic_to_shared(&sA[0][0][0]);
    unsigned baseB = (unsigned)__cvta_generic_to_shared(&sB[0][0][0]);
    const unsigned bufA = BM * ASTR * 4;     // bytes per A buffer
    const unsigned bufB = BKT * BSTR * 4;
    #pragma unroll
    for (int t = 0; t < 2; t++) {
        int i = tid + t * 256;
        a_row[t] = i >> 2;  a_cb[t] = (i & 3) * 4;
        a_src[t] = A + (size_t)(row0 + a_row[t]) * K + a_cb[t];
        a_dst[t] = baseA + (a_row[t] * ASTR + a_cb[t]) * 4;
        a_pred[t] = (row0 + a_row[t] < n) ? 16 : 0;
        b_kk[t] = i >> 5;   b_cb[t] = (i & 31) * 4;
        b_src[t] = B + (size_t)b_kk[t] * M + col0 + b_cb[t];
        b_dst[t] = baseB + (b_kk[t] * BSTR + b_cb[t]) * 4;
    }

    float acc[4][4][4];
    #pragma unroll
    for (int mi = 0; mi < 4; mi++)
        #pragma unroll
        for (int ni = 0; ni < 4; ni++)
            #pragma unroll
            for (int c = 0; c < 4; c++) acc[mi][ni][c] = 0.f;

    const int NT = K / BKT;
    // prologue: tile 0 -> buffer 0
    #pragma unroll
    for (int t = 0; t < 2; t++) {
        cp16(a_dst[t], a_src[t], a_pred[t]);
        cp16(b_dst[t], b_src[t], 16);
    }
    cp_commit();

    int buf = 0;
    for (int it = 0; it < NT; it++) {
        if (it + 1 < NT) {
            int koff = (it + 1) * BKT;
            unsigned bo = (buf ^ 1) ? 1u : 0u;
            #pragma unroll
            for (int t = 0; t < 2; t++) {
                cp16(a_dst[t] + bo * bufA, a_src[t] + koff, a_pred[t]);
                cp16(b_dst[t] + bo * bufB, b_src[t] + (size_t)koff * M, 16);
            }
            cp_commit();
            cp_wait1();
        } else {
            cp_wait0();
        }
        __syncthreads();

        #pragma unroll
        for (int kc = 0; kc < BKT; kc += 8) {
            unsigned af[4][4], bf[4][2];
            #pragma unroll
            for (int mi = 0; mi < 4; mi++) {
                int r = warp_m + mi * 16 + gid;
                int c = kc + tig;
                af[mi][0] = f2tf32(sA[buf][r][c]);
                af[mi][1] = f2tf32(sA[buf][r + 8][c]);
                af[mi][2] = f2tf32(sA[buf][r][c + 4]);
                af[mi][3] = f2tf32(sA[buf][r + 8][c + 4]);
            }
            #pragma unroll
            for (int ni = 0; ni < 4; ni++) {
                int cc = warp_n + ni * 8 + gid;
                int rr = kc + tig;
                bf[ni][0] = f2tf32(sB[buf][rr][cc]);
                bf[ni][1] = f2tf32(sB[buf][rr + 4][cc]);
            }
            #pragma unroll
            for (int mi = 0; mi < 4; mi++)
                #pragma unroll
                for (int ni = 0; ni < 4; ni++) {
                    asm volatile(
                        "mma.sync.aligned.m16n8k8.row.col.f32.tf32.tf32.f32 "
                        "{%0,%1,%2,%3}, {%4,%5,%6,%7}, {%8,%9}, {%0,%1,%2,%3};"
                        : "+f"(acc[mi][ni][0]), "+f"(acc[mi][ni][1]),
                          "+f"(acc[mi][ni][2]), "+f"(acc[mi][ni][3])
                        : "r"(af[mi][0]), "r"(af[mi][1]), "r"(af[mi][2]), "r"(af[mi][3]),
                          "r"(bf[ni][0]), "r"(bf[ni][1]));
                }
        }
        __syncthreads();
        buf ^= 1;
    }

    // epilogue: c0/c1 at (row g, col 2t..2t+1), c2/c3 at (row g+8)
    #pragma unroll
    for (int mi = 0; mi < 4; mi++) {
        int r = row0 + warp_m + mi * 16 + gid;
        #pragma unroll
        for (int ni = 0; ni < 4; ni++) {
            int c = col0 + warp_n + ni * 8 + 2 * tig;
            if (r < n)
                *(float2*)(C + (size_t)r * M + c) =
                    make_float2(acc[mi][ni][0], acc[mi][ni][1]);
            if (r + 8 < n)
                *(float2*)(C + (size_t)(r + 8) * M + c) =
                    make_float2(acc[mi][ni][2], acc[mi][ni][3]);
        }
    }
}

// ================= per-node attention scalars =================
__global__ __launch_bounds__(256) void alpha1_kernel(
    const float* __restrict__ a_src, const float* __restrict__ a_dst)
{
    int node = (blockIdx.x * blockDim.x + threadIdx.x) >> 5;
    int lane = threadIdx.x & 31;
    if (node >= NN) return;
    const float* h = &g_h1[(size_t)node * HH];
    float s[4] = {0, 0, 0, 0}, d[4] = {0, 0, 0, 0};
    #pragma unroll
    for (int k = 0; k < 8; k++) {
        int c = lane + 32 * k;
        float hv = h[c];
        s[k >> 1] += hv * a_src[c];
        d[k >> 1] += hv * a_dst[c];
    }
    #pragma unroll
    for (int hh = 0; hh < 4; hh++) { s[hh] = warp_sum(s[hh]); d[hh] = warp_sum(d[hh]); }
    if (lane == 0) {
        #pragma unroll
        for (int hh = 0; hh < 4; hh++) {
            g_as1[node * 4 + hh] = s[hh];
            g_ad1[node * 4 + hh] = d[hh];
        }
    }
}

__global__ __launch_bounds__(256) void alpha2_kernel(
    const float* __restrict__ a_src, const float* __restrict__ a_dst)
{
    int node = (blockIdx.x * blockDim.x + threadIdx.x) >> 5;
    int lane = threadIdx.x & 31;
    if (node >= NN) return;
    const float* h = &g_h2p[(size_t)node * ODIM];
    float s = 0.f, d = 0.f;
    #pragma unroll
    for (int k = 0; k < 4; k++) {
        int c = lane + 32 * k;
        float hv = h[c];
        s += hv * a_src[c];
        d += hv * a_dst[c];
    }
    s = warp_sum(s); d = warp_sum(d);
    if (lane == 0) { g_as2[node] = s; g_ad2[node] = d; }
}

// ================= fused layer1: softmax + aggregate + bias + ELU =================
__global__ __launch_bounds__(256) void agg1_kernel(const float* __restrict__ b1)
{
    int node = blockIdx.x * 8 + (threadIdx.x >> 5);
    int lane = threadIdx.x & 31;
    if (node >= NN) return;
    int beg = g_off[node], end = g_off[node + 1];

    float4 ad = *(const float4*)&g_ad1[node * 4];

    float m0 = -1e30f, m1 = -1e30f, m2 = -1e30f, m3 = -1e30f;
    for (int i = beg + lane; i < end; i += 32) {
        int s = g_csr_src[i];
        float4 as = *(const float4*)&g_as1[s * 4];
        m0 = fmaxf(m0, lrelu(as.x + ad.x));
        m1 = fmaxf(m1, lrelu(as.y + ad.y));
        m2 = fmaxf(m2, lrelu(as.z + ad.z));
        m3 = fmaxf(m3, lrelu(as.w + ad.w));
    }
    m0 = warp_max(m0); m1 = warp_max(m1); m2 = warp_max(m2); m3 = warp_max(m3);

    int ha = lane >> 4;
    float m_a = ha ? m1 : m0;
    float m_b = ha ? m3 : m2;
    float ad_a = ha ? ad.y : ad.x;
    float ad_b = ha ? ad.w : ad.z;
    // unroll x2 with independent accumulators for MLP
    float den_a0 = 0.f, den_b0 = 0.f, den_a1 = 0.f, den_b1 = 0.f;
    float4 aa0 = make_float4(0.f,0.f,0.f,0.f), ab0 = make_float4(0.f,0.f,0.f,0.f);
    float4 aa1 = make_float4(0.f,0.f,0.f,0.f), ab1 = make_float4(0.f,0.f,0.f,0.f);
    int i = beg;
    for (; i + 2 <= end; i += 2) {
        int s0 = g_csr_src[i];
        int s1 = g_csr_src[i + 1];
        float4 as0 = *(const float4*)&g_as1[s0 * 4];
        float4 as1 = *(const float4*)&g_as1[s1 * 4];
        const float4* h0 = (const float4*)&g_h1[(size_t)s0 * HH];
        const float4* h1 = (const float4*)&g_h1[(size_t)s1 * HH];
        float4 va0 = h0[lane], vb0 = h0[lane + 32];
        float4 va1 = h1[lane], vb1 = h1[lane + 32];
        float pa0 = __expf(lrelu((ha ? as0.y : as0.x) + ad_a) - m_a);
        float pb0 = __expf(lrelu((ha ? as0.w : as0.z) + ad_b) - m_b);
        float pa1 = __expf(lrelu((ha ? as1.y : as1.x) + ad_a) - m_a);
        float pb1 = __expf(lrelu((ha ? as1.w : as1.z) + ad_b) - m_b);
        den_a0 += pa0; den_b0 += pb0; den_a1 += pa1; den_b1 += pb1;
        aa0.x += pa0 * va0.x; aa0.y += pa0 * va0.y; aa0.z += pa0 * va0.z; aa0.w += pa0 * va0.w;
        ab0.x += pb0 * vb0.x; ab0.y += pb0 * vb0.y; ab0.z += pb0 * vb0.z; ab0.w += pb0 * vb0.w;
        aa1.x += pa1 * va1.x; aa1.y += pa1 * va1.y; aa1.z += pa1 * va1.z; aa1.w += pa1 * va1.w;
        ab1.x += pb1 * vb1.x; ab1.y += pb1 * vb1.y; ab1.z += pb1 * vb1.z; ab1.w += pb1 * vb1.w;
    }
    if (i < end) {
        int s0 = g_csr_src[i];
        float4 as0 = *(const float4*)&g_as1[s0 * 4];
        const float4* h0 = (const float4*)&g_h1[(size_t)s0 * HH];
        float4 va0 = h0[lane], vb0 = h0[lane + 32];
        float pa0 = __expf(lrelu((ha ? as0.y : as0.x) + ad_a) - m_a);
        float pb0 = __expf(lrelu((ha ? as0.w : as0.z) + ad_b) - m_b);
        den_a0 += pa0; den_b0 += pb0;
        aa0.x += pa0 * va0.x; aa0.y += pa0 * va0.y; aa0.z += pa0 * va0.z; aa0.w += pa0 * va0.w;
        ab0.x += pb0 * vb0.x; ab0.y += pb0 * vb0.y; ab0.z += pb0 * vb0.z; ab0.w += pb0 * vb0.w;
    }
    float ia = 1.f / (den_a0 + den_a1 + 1e-16f);
    float ib = 1.f / (den_b0 + den_b1 + 1e-16f);
    const float4* bb = (const float4*)b1;
    float4 b_a = bb[lane], b_b = bb[lane + 32];
    float4 oa, ob;
    oa.x = (aa0.x + aa1.x) * ia + b_a.x; oa.y = (aa0.y + aa1.y) * ia + b_a.y;
    oa.z = (aa0.z + aa1.z) * ia + b_a.z; oa.w = (aa0.w + aa1.w) * ia + b_a.w;
    ob.x = (ab0.x + ab1.x) * ib + b_b.x; ob.y = (ab0.y + ab1.y) * ib + b_b.y;
    ob.z = (ab0.z + ab1.z) * ib + b_b.z; ob.w = (ab0.w + ab1.w) * ib + b_b.w;
    oa.x = oa.x > 0.f ? oa.x : (__expf(oa.x) - 1.f);
    oa.y = oa.y > 0.f ? oa.y : (__expf(oa.y) - 1.f);
    oa.z = oa.z > 0.f ? oa.z : (__expf(oa.z) - 1.f);
    oa.w = oa.w > 0.f ? oa.w : (__expf(oa.w) - 1.f);
    ob.x = ob.x > 0.f ? ob.x : (__expf(ob.x) - 1.f);
    ob.y = ob.y > 0.f ? ob.y : (__expf(ob.y) - 1.f);
    ob.z = ob.z > 0.f ? ob.z : (__expf(ob.z) - 1.f);
    ob.w = ob.w > 0.f ? ob.w : (__expf(ob.w) - 1.f);
    float4* og = (float4*)&g_agg1[(size_t)node * HH];
    og[lane] = oa;
    og[lane + 32] = ob;
}

// ================= fused layer2: softmax + aggregate + bias + L2 normalize ======
__global__ __launch_bounds__(256) void agg2_kernel(
    float* __restrict__ out, const float* __restrict__ b2)
{
    int node = blockIdx.x * 8 + (threadIdx.x >> 5);
    int lane = threadIdx.x & 31;
    if (node >= NN) return;
    int beg = g_off[node], end = g_off[node + 1];

    float ad = g_ad2[node];

    float m = -1e30f;
    for (int i = beg + lane; i < end; i += 32) {
        int s = g_csr_src[i];
        m = fmaxf(m, lrelu(g_as2[s] + ad));
    }
    m = warp_max(m);

    float den0 = 0.f, den1 = 0.f;
    float4 ac0 = make_float4(0.f,0.f,0.f,0.f), ac1 = make_float4(0.f,0.f,0.f,0.f);
    int i = beg;
    for (; i + 2 <= end; i += 2) {
        int s0 = g_csr_src[i];
        int s1 = g_csr_src[i + 1];
        float l0 = g_as2[s0], l1 = g_as2[s1];
        float4 v0 = ((const float4*)&g_h2p[(size_t)s0 * ODIM])[lane];
        float4 v1 = ((const float4*)&g_h2p[(size_t)s1 * ODIM])[lane];
        float p0 = __expf(lrelu(l0 + ad) - m);
        float p1 = __expf(lrelu(l1 + ad) - m);
        den0 += p0; den1 += p1;
        ac0.x += p0 * v0.x; ac0.y += p0 * v0.y; ac0.z += p0 * v0.z; ac0.w += p0 * v0.w;
        ac1.x += p1 * v1.x; ac1.y += p1 * v1.y; ac1.z += p1 * v1.z; ac1.w += p1 * v1.w;
    }
    if (i < end) {
        int s0 = g_csr_src[i];
        float p0 = __expf(lrelu(g_as2[s0] + ad) - m);
        float4 v0 = ((const float4*)&g_h2p[(size_t)s0 * ODIM])[lane];
        den0 += p0;
        ac0.x += p0 * v0.x; ac0.y += p0 * v0.y; ac0.z += p0 * v0.z; ac0.w += p0 * v0.w;
    }
    float iv = 1.f / (den0 + den1 + 1e-16f);
    float4 b = ((const float4*)b2)[lane];
    float4 v;
    v.x = (ac0.x + ac1.x) * iv + b.x; v.y = (ac0.y + ac1.y) * iv + b.y;
    v.z = (ac0.z + ac1.z) * iv + b.z; v.w = (ac0.w + ac1.w) * iv + b.w;
    float ss = warp_sum(v.x * v.x + v.y * v.y + v.z * v.z + v.w * v.w);
    float sc = 1.f / fmaxf(sqrtf(ss), 1e-12f);
    v.x *= sc; v.y *= sc; v.z *= sc; v.w *= sc;
    ((float4*)(out + (size_t)node * ODIM))[lane] = v;
}

// ================= host =================
extern "C" void kernel_launch(void* const* d_in, const int* in_sizes, int n_in,
                              void* d_out, int out_size)
{
    const float* x      = (const float*)d_in[0];
    const int*   ei     = (const int*)d_in[1];     // int32 (JAX x64 disabled)
    const float* W1     = (const float*)d_in[2];
    const float* a_src1 = (const float*)d_in[3];
    const float* a_dst1 = (const float*)d_in[4];
    const float* b1     = (const float*)d_in[5];
    const float* W2     = (const float*)d_in[6];
    const float* a_src2 = (const float*)d_in[7];
    const float* a_dst2 = (const float*)d_in[8];
    const float* b2     = (const float*)d_in[9];
    float*       out    = (float*)d_out;
    const int*   srcp   = ei;
    const int*   dstp   = ei + NE;

    void* p_deg;
    cudaGetSymbolAddress(&p_deg, g_deg);
    void *p_h1, *p_agg1, *p_h2p;
    cudaGetSymbolAddress(&p_h1,   g_h1);
    cudaGetSymbolAddress(&p_agg1, g_agg1);
    cudaGetSymbolAddress(&p_h2p,  g_h2p);

    cudaStream_t st = 0;
    const int EB = (TE + 255) / 256;
    const int MBLK = (NN + BM - 1) / BM;   // 391

    // ---- CSR build (by dst) ----
    cudaMemsetAsync(p_deg, 0, sizeof(int) * NN, st);
    hist_kernel<<<EB, 256, 0, st>>>(srcp, dstp);
    scan_kernel<<<1, SCAN_T, 0, st>>>();
    scatter_kernel<<<EB, 256, 0, st>>>(srcp, dstp);

    // ---- layer 1 ----
    gemm_tf32_kernel<<<dim3(MBLK, 2), 256, 0, st>>>(x, W1, (float*)p_h1, NN, IN_DIM, HH);
    alpha1_kernel<<<(NN * 32 + 255) / 256, 256, 0, st>>>(a_src1, a_dst1);
    agg1_kernel<<<(NN + 7) / 8, 256, 0, st>>>(b1);

    // ---- layer 2 ----
    gemm_tf32_kernel<<<dim3(MBLK, 1), 256, 0, st>>>((const float*)p_agg1, W2,
                                                    (float*)p_h2p, NN, HH, ODIM);
    alpha2_kernel<<<(NN * 32 + 255) / 256, 256, 0, st>>>(a_src2, a_dst2);
    agg2_kernel<<<(NN + 7) / 8, 256, 0, st>>>(out, b2);
}

// round 14
// speedup vs baseline: 2.6313x; 1.0834x over previous
#include <cuda_runtime.h>
#include <cuda_fp16.h>
#include <math.h>

#define NN 50000
#define NE 800000
#define TE (NE + NN)          // edges + self loops
#define IN_DIM 128
#define HH 256                // HEADS*HID
#define ODIM 128
#define NEG_SLOPE 0.2f

// ---------------- scratch (device globals; no allocs allowed) ----------------
__device__ __align__(16) __half g_h1h[(size_t)NN * HH];    // layer1 projection (fp16)
__device__ __align__(16) float  g_agg1[(size_t)NN * HH];   // layer1 out (post ELU) = layer2 in
__device__ __align__(16) __half g_h2ph[(size_t)NN * ODIM]; // layer2 projection (fp16)
__device__ __align__(16) float  g_as1[NN * 4];
__device__ __align__(16) float  g_ad1[NN * 4];
__device__ __align__(16) float  g_as2[NN];
__device__ __align__(16) float  g_ad2[NN];
// CSR (by destination node)
__device__ int g_deg[NN];
__device__ int g_off[NN + 1];
__device__ int g_cur[NN];
__device__ int g_csr_src[TE];

// ---------------- helpers ----------------
__device__ __forceinline__ float warp_sum(float v) {
    #pragma unroll
    for (int off = 16; off; off >>= 1) v += __shfl_xor_sync(0xffffffffu, v, off);
    return v;
}
__device__ __forceinline__ float warp_max(float v) {
    #pragma unroll
    for (int off = 16; off; off >>= 1) v = fmaxf(v, __shfl_xor_sync(0xffffffffu, v, off));
    return v;
}
__device__ __forceinline__ float lrelu(float v) {
    return v > 0.f ? v : NEG_SLOPE * v;
}
__device__ __forceinline__ bool edge_sd(int e, const int* __restrict__ src,
                                        const int* __restrict__ dst, int& s, int& d) {
    if (e < NE) { s = src[e]; d = dst[e]; } else { s = d = e - NE; }
    return ((unsigned)s < (unsigned)NN) && ((unsigned)d < (unsigned)NN);
}
__device__ __forceinline__ unsigned f2tf32(float f) {
    unsigned u;
    asm("cvt.rna.tf32.f32 %0, %1;" : "=r"(u) : "f"(f));
    return u;
}
__device__ __forceinline__ void cp16(unsigned dst, const void* src, int src_bytes) {
    asm volatile("cp.async.ca.shared.global [%0], [%1], 16, %2;"
                 :: "r"(dst), "l"(src), "r"(src_bytes));
}
__device__ __forceinline__ void cp_commit() { asm volatile("cp.async.commit_group;"); }
__device__ __forceinline__ void cp_wait0()  { asm volatile("cp.async.wait_group 0;"); }
__device__ __forceinline__ void cp_wait1()  { asm volatile("cp.async.wait_group 1;"); }
__device__ __forceinline__ float sel4(float4 v, int head) {
    return (head & 2) ? ((head & 1) ? v.w : v.z) : ((head & 1) ? v.y : v.x);
}

// ================= CSR build =================
__global__ __launch_bounds__(256) void hist_kernel(
    const int* __restrict__ src, const int* __restrict__ dst)
{
    int e = blockIdx.x * blockDim.x + threadIdx.x;
    if (e >= TE) return;
    int s, d;
    if (!edge_sd(e, src, dst, s, d)) return;
    atomicAdd(&g_deg[d], 1);
}

#define SCAN_T 1024
#define CHUNK ((NN + SCAN_T - 1) / SCAN_T)     // 49
__global__ __launch_bounds__(SCAN_T) void scan_kernel()
{
    __shared__ int warp_tot[32];
    int tid = threadIdx.x;
    int lane = tid & 31;
    int wid = tid >> 5;
    int t0 = tid * CHUNK;

    int local[CHUNK];
    int sum = 0;
    #pragma unroll
    for (int i = 0; i < CHUNK; i++) {
        int idx = t0 + i;
        int v = (idx < NN) ? g_deg[idx] : 0;
        local[i] = v;
        sum += v;
    }
    int incl = sum;
    #pragma unroll
    for (int off = 1; off < 32; off <<= 1) {
        int t = __shfl_up_sync(0xffffffffu, incl, off);
        if (lane >= off) incl += t;
    }
    if (lane == 31) warp_tot[wid] = incl;
    __syncthreads();
    if (wid == 0) {
        int w = warp_tot[lane];
        #pragma unroll
        for (int off = 1; off < 32; off <<= 1) {
            int t = __shfl_up_sync(0xffffffffu, w, off);
            if (lane >= off) w += t;
        }
        warp_tot[lane] = w;
    }
    __syncthreads();
    int pre = incl - sum + (wid ? warp_tot[wid - 1] : 0);
    #pragma unroll
    for (int i = 0; i < CHUNK; i++) {
        int idx = t0 + i;
        if (idx < NN) { g_off[idx] = pre; g_cur[idx] = pre; }
        pre += local[i];
    }
    if (tid == SCAN_T - 1) g_off[NN] = pre;
}

__global__ __launch_bounds__(256) void scatter_kernel(
    const int* __restrict__ src, const int* __restrict__ dst)
{
    int e = blockIdx.x * blockDim.x + threadIdx.x;
    if (e >= TE) return;
    int s, d;
    if (!edge_sd(e, src, dst, s, d)) return;
    int pos = atomicAdd(&g_cur[d], 1);
    g_csr_src[pos] = s;
}

// ================= tf32 tensor-core GEMM: C[n,M] = A[n,K] @ B[K,M] =================
// 128x128x16 tile, 256 threads (8 warps, 2x4), warp 64x32 via m16n8k8 mma.
// cp.async double-buffered. Output fp16 (HOUT=true) or fp32.
#define BM 128
#define BN 128
#define BKT 16
#define APAD 4
#define BPAD 8
#define ASTR (BKT + APAD)     // 20
#define BSTR (BN + BPAD)      // 136
template <bool HOUT>
__global__ __launch_bounds__(256) void gemm_tf32_kernel(
    const float* __restrict__ A, const float* __restrict__ B,
    void* __restrict__ Cv, int n, int K, int M)
{
    __shared__ float sA[2][BM][ASTR];
    __shared__ float sB[2][BKT][BSTR];
    int tid = threadIdx.x;
    int lane = tid & 31, wid = tid >> 5;
    int warp_m = (wid >> 2) * 64;
    int warp_n = (wid & 3) * 32;
    int row0 = blockIdx.x * BM, col0 = blockIdx.y * BN;
    int gid = lane >> 2;
    int tig = lane & 3;

    int a_row[2], b_kk[2], b_cb[2];
    const float *a_src[2], *b_src[2];
    unsigned a_dst[2], b_dst[2];
    int a_pred[2];
    unsigned baseA = (unsigned)__cvta_generic_to_shared(&sA[0][0][0]);
    unsigned baseB = (unsigned)__cvta_generic_to_shared(&sB[0][0][0]);
    const unsigned bufA = BM * ASTR * 4;
    const unsigned bufB = BKT * BSTR * 4;
    #pragma unroll
    for (int t = 0; t < 2; t++) {
        int i = tid + t * 256;
        a_row[t] = i >> 2;  int acb = (i & 3) * 4;
        a_src[t] = A + (size_t)(row0 + a_row[t]) * K + acb;
        a_dst[t] = baseA + (a_row[t] * ASTR + acb) * 4;
        a_pred[t] = (row0 + a_row[t] < n) ? 16 : 0;
        b_kk[t] = i >> 5;   b_cb[t] = (i & 31) * 4;
        b_src[t] = B + (size_t)b_kk[t] * M + col0 + b_cb[t];
        b_dst[t] = baseB + (b_kk[t] * BSTR + b_cb[t]) * 4;
    }

    float acc[4][4][4];
    #pragma unroll
    for (int mi = 0; mi < 4; mi++)
        #pragma unroll
        for (int ni = 0; ni < 4; ni++)
            #pragma unroll
            for (int c = 0; c < 4; c++) acc[mi][ni][c] = 0.f;

    const int NT = K / BKT;
    #pragma unroll
    for (int t = 0; t < 2; t++) {
        cp16(a_dst[t], a_src[t], a_pred[t]);
        cp16(b_dst[t], b_src[t], 16);
    }
    cp_commit();

    int buf = 0;
    for (int it = 0; it < NT; it++) {
        if (it + 1 < NT) {
            int koff = (it + 1) * BKT;
            unsigned bo = (unsigned)(buf ^ 1);
            #pragma unroll
            for (int t = 0; t < 2; t++) {
                cp16(a_dst[t] + bo * bufA, a_src[t] + koff, a_pred[t]);
                cp16(b_dst[t] + bo * bufB, b_src[t] + (size_t)koff * M, 16);
            }
            cp_commit();
            cp_wait1();
        } else {
            cp_wait0();
        }
        __syncthreads();

        #pragma unroll
        for (int kc = 0; kc < BKT; kc += 8) {
            unsigned af[4][4], bf[4][2];
            #pragma unroll
            for (int mi = 0; mi < 4; mi++) {
                int r = warp_m + mi * 16 + gid;
                int c = kc + tig;
                af[mi][0] = f2tf32(sA[buf][r][c]);
                af[mi][1] = f2tf32(sA[buf][r + 8][c]);
                af[mi][2] = f2tf32(sA[buf][r][c + 4]);
                af[mi][3] = f2tf32(sA[buf][r + 8][c + 4]);
            }
            #pragma unroll
            for (int ni = 0; ni < 4; ni++) {
                int cc = warp_n + ni * 8 + gid;
                int rr = kc + tig;
                bf[ni][0] = f2tf32(sB[buf][rr][cc]);
                bf[ni][1] = f2tf32(sB[buf][rr + 4][cc]);
            }
            #pragma unroll
            for (int mi = 0; mi < 4; mi++)
                #pragma unroll
                for (int ni = 0; ni < 4; ni++) {
                    asm volatile(
                        "mma.sync.aligned.m16n8k8.row.col.f32.tf32.tf32.f32 "
                        "{%0,%1,%2,%3}, {%4,%5,%6,%7}, {%8,%9}, {%0,%1,%2,%3};"
                        : "+f"(acc[mi][ni][0]), "+f"(acc[mi][ni][1]),
                          "+f"(acc[mi][ni][2]), "+f"(acc[mi][ni][3])
                        : "r"(af[mi][0]), "r"(af[mi][1]), "r"(af[mi][2]), "r"(af[mi][3]),
                          "r"(bf[ni][0]), "r"(bf[ni][1]));
                }
        }
        __syncthreads();
        buf ^= 1;
    }

    #pragma unroll
    for (int mi = 0; mi < 4; mi++) {
        int r = row0 + warp_m + mi * 16 + gid;
        #pragma unroll
        for (int ni = 0; ni < 4; ni++) {
            int c = col0 + warp_n + ni * 8 + 2 * tig;
            if (HOUT) {
                __half* C = (__half*)Cv;
                if (r < n)
                    *(__half2*)(C + (size_t)r * M + c) =
                        __floats2half2_rn(acc[mi][ni][0], acc[mi][ni][1]);
                if (r + 8 < n)
                    *(__half2*)(C + (size_t)(r + 8) * M + c) =
                        __floats2half2_rn(acc[mi][ni][2], acc[mi][ni][3]);
            } else {
                float* C = (float*)Cv;
                if (r < n)
                    *(float2*)(C + (size_t)r * M + c) =
                        make_float2(acc[mi][ni][0], acc[mi][ni][1]);
                if (r + 8 < n)
                    *(float2*)(C + (size_t)(r + 8) * M + c) =
                        make_float2(acc[mi][ni][2], acc[mi][ni][3]);
            }
        }
    }
}

// ================= per-node attention scalars (fp16 features) =================
__global__ __launch_bounds__(256) void alpha1_kernel(
    const float* __restrict__ a_src, const float* __restrict__ a_dst)
{
    int node = (blockIdx.x * blockDim.x + threadIdx.x) >> 5;
    int lane = threadIdx.x & 31;
    if (node >= NN) return;
    // lane owns features 8*lane .. 8*lane+7 (all in head lane>>3)
    uint4 q = ((const uint4*)(g_h1h + (size_t)node * HH))[lane];
    float2 f0 = __half22float2(*(__half2*)&q.x);
    float2 f1 = __half22float2(*((__half2*)&q.x + 1));
    float2 f2 = __half22float2(*(__half2*)&q.z);
    float2 f3 = __half22float2(*((__half2*)&q.z + 1));
    float4 wa0 = *(const float4*)(a_src + 8 * lane);
    float4 wa1 = *(const float4*)(a_src + 8 * lane + 4);
    float4 wd0 = *(const float4*)(a_dst + 8 * lane);
    float4 wd1 = *(const float4*)(a_dst + 8 * lane + 4);
    float s = f0.x * wa0.x + f0.y * wa0.y + f1.x * wa0.z + f1.y * wa0.w
            + f2.x * wa1.x + f2.y * wa1.y + f3.x * wa1.z + f3.y * wa1.w;
    float d = f0.x * wd0.x + f0.y * wd0.y + f1.x * wd0.z + f1.y * wd0.w
            + f2.x * wd1.x + f2.y * wd1.y + f3.x * wd1.z + f3.y * wd1.w;
    #pragma unroll
    for (int off = 1; off < 8; off <<= 1) {
        s += __shfl_xor_sync(0xffffffffu, s, off);
        d += __shfl_xor_sync(0xffffffffu, d, off);
    }
    if ((lane & 7) == 0) {
        int head = lane >> 3;
        g_as1[node * 4 + head] = s;
        g_ad1[node * 4 + head] = d;
    }
}

__global__ __launch_bounds__(256) void alpha2_kernel(
    const float* __restrict__ a_src, const float* __restrict__ a_dst)
{
    int node = (blockIdx.x * blockDim.x + threadIdx.x) >> 5;
    int lane = threadIdx.x & 31;
    if (node >= NN) return;
    uint2 q = ((const uint2*)(g_h2ph + (size_t)node * ODIM))[lane];
    float2 f0 = __half22float2(*(__half2*)&q.x);
    float2 f1 = __half22float2(*(__half2*)&q.y);
    float4 wa = *(const float4*)(a_src + 4 * lane);
    float4 wd = *(const float4*)(a_dst + 4 * lane);
    float s = f0.x * wa.x + f0.y * wa.y + f1.x * wa.z + f1.y * wa.w;
    float d = f0.x * wd.x + f0.y * wd.y + f1.x * wd.z + f1.y * wd.w;
    s = warp_sum(s); d = warp_sum(d);
    if (lane == 0) { g_as2[node] = s; g_ad2[node] = d; }
}

// ================= fused layer1: softmax + aggregate + bias + ELU =================
// one warp per dst node; lane owns 8 contiguous features (head = lane>>3)
__global__ __launch_bounds__(256) void agg1_kernel(const float* __restrict__ b1)
{
    int node = blockIdx.x * 8 + (threadIdx.x >> 5);
    int lane = threadIdx.x & 31;
    if (node >= NN) return;
    int beg = g_off[node], end = g_off[node + 1];

    float4 ad = *(const float4*)&g_ad1[node * 4];

    float m0 = -1e30f, m1 = -1e30f, m2 = -1e30f, m3 = -1e30f;
    for (int i = beg + lane; i < end; i += 32) {
        int s = g_csr_src[i];
        float4 as = *(const float4*)&g_as1[s * 4];
        m0 = fmaxf(m0, lrelu(as.x + ad.x));
        m1 = fmaxf(m1, lrelu(as.y + ad.y));
        m2 = fmaxf(m2, lrelu(as.z + ad.z));
        m3 = fmaxf(m3, lrelu(as.w + ad.w));
    }
    m0 = warp_max(m0); m1 = warp_max(m1); m2 = warp_max(m2); m3 = warp_max(m3);

    int head = lane >> 3;
    float m_sel  = (head & 2) ? ((head & 1) ? m3 : m2) : ((head & 1) ? m1 : m0);
    float ad_sel = sel4(ad, head);

    float den0 = 0.f, den1 = 0.f;
    float a0 = 0.f, a1 = 0.f, a2 = 0.f, a3 = 0.f,
          a4 = 0.f, a5 = 0.f, a6 = 0.f, a7 = 0.f;
    int i = beg;
    for (; i + 2 <= end; i += 2) {
        int s0 = g_csr_src[i];
        int s1 = g_csr_src[i + 1];
        float4 as0 = *(const float4*)&g_as1[s0 * 4];
        float4 as1 = *(const float4*)&g_as1[s1 * 4];
        uint4 q0 = ((const uint4*)(g_h1h + (size_t)s0 * HH))[lane];
        uint4 q1 = ((const uint4*)(g_h1h + (size_t)s1 * HH))[lane];
        float p0 = __expf(lrelu(sel4(as0, head) + ad_sel) - m_sel);
        float p1 = __expf(lrelu(sel4(as1, head) + ad_sel) - m_sel);
        den0 += p0; den1 += p1;
        float2 v;
        v = __half22float2(*(__half2*)&q0.x);        a0 += p0 * v.x; a1 += p0 * v.y;
        v = __half22float2(*((__half2*)&q0.x + 1));  a2 += p0 * v.x; a3 += p0 * v.y;
        v = __half22float2(*(__half2*)&q0.z);        a4 += p0 * v.x; a5 += p0 * v.y;
        v = __half22float2(*((__half2*)&q0.z + 1));  a6 += p0 * v.x; a7 += p0 * v.y;
        v = __half22float2(*(__half2*)&q1.x);        a0 += p1 * v.x; a1 += p1 * v.y;
        v = __half22float2(*((__half2*)&q1.x + 1));  a2 += p1 * v.x; a3 += p1 * v.y;
        v = __half22float2(*(__half2*)&q1.z);        a4 += p1 * v.x; a5 += p1 * v.y;
        v = __half22float2(*((__half2*)&q1.z + 1));  a6 += p1 * v.x; a7 += p1 * v.y;
    }
    if (i < end) {
        int s0 = g_csr_src[i];
        float4 as0 = *(const float4*)&g_as1[s0 * 4];
        uint4 q0 = ((const uint4*)(g_h1h + (size_t)s0 * HH))[lane];
        float p0 = __expf(lrelu(sel4(as0, head) + ad_sel) - m_sel);
        den0 += p0;
        float2 v;
        v = __half22float2(*(__half2*)&q0.x);        a0 += p0 * v.x; a1 += p0 * v.y;
        v = __half22float2(*((__half2*)&q0.x + 1));  a2 += p0 * v.x; a3 += p0 * v.y;
        v = __half22float2(*(__half2*)&q0.z);        a4 += p0 * v.x; a5 += p0 * v.y;
        v = __half22float2(*((__half2*)&q0.z + 1));  a6 += p0 * v.x; a7 += p0 * v.y;
    }
    float iv = 1.f / (den0 + den1 + 1e-16f);
    float4 bb0 = *(const float4*)(b1 + 8 * lane);
    float4 bb1 = *(const float4*)(b1 + 8 * lane + 4);
    float o0 = a0 * iv + bb0.x, o1 = a1 * iv + bb0.y;
    float o2 = a2 * iv + bb0.z, o3 = a3 * iv + bb0.w;
    float o4 = a4 * iv + bb1.x, o5 = a5 * iv + bb1.y;
    float o6 = a6 * iv + bb1.z, o7 = a7 * iv + bb1.w;
    o0 = o0 > 0.f ? o0 : (__expf(o0) - 1.f);
    o1 = o1 > 0.f ? o1 : (__expf(o1) - 1.f);
    o2 = o2 > 0.f ? o2 : (__expf(o2) - 1.f);
    o3 = o3 > 0.f ? o3 : (__expf(o3) - 1.f);
    o4 = o4 > 0.f ? o4 : (__expf(o4) - 1.f);
    o5 = o5 > 0.f ? o5 : (__expf(o5) - 1.f);
    o6 = o6 > 0.f ? o6 : (__expf(o6) - 1.f);
    o7 = o7 > 0.f ? o7 : (__expf(o7) - 1.f);
    float* og = &g_agg1[(size_t)node * HH + 8 * lane];
    *(float4*)og       = make_float4(o0, o1, o2, o3);
    *(float4*)(og + 4) = make_float4(o4, o5, o6, o7);
}

// ================= fused layer2: softmax + aggregate + bias + L2 normalize ======
// lane owns 4 contiguous features
__global__ __launch_bounds__(256) void agg2_kernel(
    float* __restrict__ out, const float* __restrict__ b2)
{
    int node = blockIdx.x * 8 + (threadIdx.x >> 5);
    int lane = threadIdx.x & 31;
    if (node >= NN) return;
    int beg = g_off[node], end = g_off[node + 1];

    float ad = g_ad2[node];

    float m = -1e30f;
    for (int i = beg + lane; i < end; i += 32) {
        int s = g_csr_src[i];
        m = fmaxf(m, lrelu(g_as2[s] + ad));
    }
    m = warp_max(m);

    float den0 = 0.f, den1 = 0.f;
    float a0 = 0.f, a1 = 0.f, a2 = 0.f, a3 = 0.f;
    int i = beg;
    for (; i + 2 <= end; i += 2) {
        int s0 = g_csr_src[i];
        int s1 = g_csr_src[i + 1];
        float l0 = g_as2[s0], l1 = g_as2[s1];
        uint2 q0 = ((const uint2*)(g_h2ph + (size_t)s0 * ODIM))[lane];
        uint2 q1 = ((const uint2*)(g_h2ph + (size_t)s1 * ODIM))[lane];
        float p0 = __expf(lrelu(l0 + ad) - m);
        float p1 = __expf(lrelu(l1 + ad) - m);
        den0 += p0; den1 += p1;
        float2 v;
        v = __half22float2(*(__half2*)&q0.x); a0 += p0 * v.x; a1 += p0 * v.y;
        v = __half22float2(*(__half2*)&q0.y); a2 += p0 * v.x; a3 += p0 * v.y;
        v = __half22float2(*(__half2*)&q1.x); a0 += p1 * v.x; a1 += p1 * v.y;
        v = __half22float2(*(__half2*)&q1.y); a2 += p1 * v.x; a3 += p1 * v.y;
    }
    if (i < end) {
        int s0 = g_csr_src[i];
        uint2 q0 = ((const uint2*)(g_h2ph + (size_t)s0 * ODIM))[lane];
        float p0 = __expf(lrelu(g_as2[s0] + ad) - m);
        den0 += p0;
        float2 v;
        v = __half22float2(*(__half2*)&q0.x); a0 += p0 * v.x; a1 += p0 * v.y;
        v = __half22float2(*(__half2*)&q0.y); a2 += p0 * v.x; a3 += p0 * v.y;
    }
    float iv = 1.f / (den0 + den1 + 1e-16f);
    float4 b = *(const float4*)(b2 + 4 * lane);
    float4 v4;
    v4.x = a0 * iv + b.x; v4.y = a1 * iv + b.y;
    v4.z = a2 * iv + b.z; v4.w = a3 * iv + b.w;
    float ss = warp_sum(v4.x * v4.x + v4.y * v4.y + v4.z * v4.z + v4.w * v4.w);
    float sc = 1.f / fmaxf(sqrtf(ss), 1e-12f);
    v4.x *= sc; v4.y *= sc; v4.z *= sc; v4.w *= sc;
    *(float4*)(out + (size_t)node * ODIM + 4 * lane) = v4;
}

// ================= host =================
extern "C" void kernel_launch(void* const* d_in, const int* in_sizes, int n_in,
                              void* d_out, int out_size)
{
    const float* x      = (const float*)d_in[0];
    const int*   ei     = (const int*)d_in[1];     // int32 (JAX x64 disabled)
    const float* W1     = (const float*)d_in[2];
    const float* a_src1 = (const float*)d_in[3];
    const float* a_dst1 = (const float*)d_in[4];
    const float* b1     = (const float*)d_in[5];
    const float* W2     = (const float*)d_in[6];
    const float* a_src2 = (const float*)d_in[7];
    const float* a_dst2 = (const float*)d_in[8];
    const float* b2     = (const float*)d_in[9];
    float*       out    = (float*)d_out;
    const int*   srcp   = ei;
    const int*   dstp   = ei + NE;

    void* p_deg;
    cudaGetSymbolAddress(&p_deg, g_deg);
    void *p_h1h, *p_agg1, *p_h2ph;
    cudaGetSymbolAddress(&p_h1h,  g_h1h);
    cudaGetSymbolAddress(&p_agg1, g_agg1);
    cudaGetSymbolAddress(&p_h2ph, g_h2ph);

    cudaStream_t st = 0;
    const int EB = (TE + 255) / 256;
    const int MBLK = (NN + BM - 1) / BM;   // 391

    // ---- CSR build (by dst) ----
    cudaMemsetAsync(p_deg, 0, sizeof(int) * NN, st);
    hist_kernel<<<EB, 256, 0, st>>>(srcp, dstp);
    scan_kernel<<<1, SCAN_T, 0, st>>>();
    scatter_kernel<<<EB, 256, 0, st>>>(srcp, dstp);

    // ---- layer 1 ----
    gemm_tf32_kernel<true><<<dim3(MBLK, 2), 256, 0, st>>>(x, W1, p_h1h, NN, IN_DIM, HH);
    alpha1_kernel<<<(NN * 32 + 255) / 256, 256, 0, st>>>(a_src1, a_dst1);
    agg1_kernel<<<(NN + 7) / 8, 256, 0, st>>>(b1);

    // ---- layer 2 ----
    gemm_tf32_kernel<true><<<dim3(MBLK, 1), 256, 0, st>>>((const float*)p_agg1, W2,
                                                          p_h2ph, NN, HH, ODIM);
    alpha2_kernel<<<(NN * 32 + 255) / 256, 256, 0, st>>>(a_src2, a_dst2);
    agg2_kernel<<<(NN + 7) / 8, 256, 0, st>>>(out, b2);
}

// round 17
// speedup vs baseline: 2.7199x; 1.0336x over previous
#include <cuda_runtime.h>
#include <cuda_fp16.h>
#include <math.h>

#define NN 50000
#define NE 800000
#define TE (NE + NN)          // edges + self loops
#define IN_DIM 128
#define HH 256                // HEADS*HID
#define ODIM 128
#define NEG_SLOPE 0.2f

// ---------------- scratch (device globals; no allocs allowed) ----------------
__device__ __align__(16) __half g_h1h[(size_t)NN * HH];    // layer1 projection (fp16)
__device__ __align__(16) float  g_agg1[(size_t)NN * HH];   // layer1 out (post ELU) = layer2 in
__device__ __align__(16) __half g_h2ph[(size_t)NN * ODIM]; // layer2 projection (fp16)
__device__ __align__(16) float  g_as1[NN * 4];
__device__ __align__(16) float  g_ad1[NN * 4];
__device__ __align__(16) float  g_as2[NN];
__device__ __align__(16) float  g_ad2[NN];
// CSR (by destination node)
__device__ int g_deg[NN];
__device__ int g_off[NN + 1];
__device__ int g_cur[NN];
__device__ int g_csr_src[TE];

// ---------------- helpers ----------------
__device__ __forceinline__ float warp_sum(float v) {
    #pragma unroll
    for (int off = 16; off; off >>= 1) v += __shfl_xor_sync(0xffffffffu, v, off);
    return v;
}
__device__ __forceinline__ float warp_max(float v) {
    #pragma unroll
    for (int off = 16; off; off >>= 1) v = fmaxf(v, __shfl_xor_sync(0xffffffffu, v, off));
    return v;
}
__device__ __forceinline__ float lrelu(float v) {
    return v > 0.f ? v : NEG_SLOPE * v;
}
__device__ __forceinline__ bool edge_sd(int e, const int* __restrict__ src,
                                        const int* __restrict__ dst, int& s, int& d) {
    if (e < NE) { s = src[e]; d = dst[e]; } else { s = d = e - NE; }
    return ((unsigned)s < (unsigned)NN) && ((unsigned)d < (unsigned)NN);
}
__device__ __forceinline__ unsigned f2tf32(float f) {
    unsigned u;
    asm("cvt.rna.tf32.f32 %0, %1;" : "=r"(u) : "f"(f));
    return u;
}
__device__ __forceinline__ void cp16(unsigned dst, const void* src, int src_bytes) {
    asm volatile("cp.async.ca.shared.global [%0], [%1], 16, %2;"
                 :: "r"(dst), "l"(src), "r"(src_bytes));
}
__device__ __forceinline__ void cp_commit() { asm volatile("cp.async.commit_group;"); }
__device__ __forceinline__ void cp_wait0()  { asm volatile("cp.async.wait_group 0;"); }
__device__ __forceinline__ void cp_wait1()  { asm volatile("cp.async.wait_group 1;"); }
__device__ __forceinline__ float sel4(float4 v, int head) {
    return (head & 2) ? ((head & 1) ? v.w : v.z) : ((head & 1) ? v.y : v.x);
}

// ================= CSR build =================
__global__ __launch_bounds__(256) void hist_kernel(
    const int* __restrict__ src, const int* __restrict__ dst)
{
    int e = blockIdx.x * blockDim.x + threadIdx.x;
    if (e >= TE) return;
    int s, d;
    if (!edge_sd(e, src, dst, s, d)) return;
    atomicAdd(&g_deg[d], 1);
}

#define SCAN_T 1024
#define CHUNK ((NN + SCAN_T - 1) / SCAN_T)     // 49
__global__ __launch_bounds__(SCAN_T) void scan_kernel()
{
    __shared__ int warp_tot[32];
    int tid = threadIdx.x;
    int lane = tid & 31;
    int wid = tid >> 5;
    int t0 = tid * CHUNK;

    int local[CHUNK];
    int sum = 0;
    #pragma unroll
    for (int i = 0; i < CHUNK; i++) {
        int idx = t0 + i;
        int v = (idx < NN) ? g_deg[idx] : 0;
        local[i] = v;
        sum += v;
    }
    int incl = sum;
    #pragma unroll
    for (int off = 1; off < 32; off <<= 1) {
        int t = __shfl_up_sync(0xffffffffu, incl, off);
        if (lane >= off) incl += t;
    }
    if (lane == 31) warp_tot[wid] = incl;
    __syncthreads();
    if (wid == 0) {
        int w = warp_tot[lane];
        #pragma unroll
        for (int off = 1; off < 32; off <<= 1) {
            int t = __shfl_up_sync(0xffffffffu, w, off);
            if (lane >= off) w += t;
        }
        warp_tot[lane] = w;
    }
    __syncthreads();
    int pre = incl - sum + (wid ? warp_tot[wid - 1] : 0);
    #pragma unroll
    for (int i = 0; i < CHUNK; i++) {
        int idx = t0 + i;
        if (idx < NN) { g_off[idx] = pre; g_cur[idx] = pre; }
        pre += local[i];
    }
    if (tid == SCAN_T - 1) g_off[NN] = pre;
}

__global__ __launch_bounds__(256) void scatter_kernel(
    const int* __restrict__ src, const int* __restrict__ dst)
{
    int e = blockIdx.x * blockDim.x + threadIdx.x;
    if (e >= TE) return;
    int s, d;
    if (!edge_sd(e, src, dst, s, d)) return;
    int pos = atomicAdd(&g_cur[d], 1);
    g_csr_src[pos] = s;
}

// ================= tf32 tensor-core GEMM: C[n,M] = A[n,K] @ B[K,M] =================
#define BM 128
#define BN 128
#define BKT 16
#define APAD 4
#define BPAD 8
#define ASTR (BKT + APAD)     // 20
#define BSTR (BN + BPAD)      // 136
template <bool HOUT>
__global__ __launch_bounds__(256) void gemm_tf32_kernel(
    const float* __restrict__ A, const float* __restrict__ B,
    void* __restrict__ Cv, int n, int K, int M)
{
    __shared__ float sA[2][BM][ASTR];
    __shared__ float sB[2][BKT][BSTR];
    int tid = threadIdx.x;
    int lane = tid & 31, wid = tid >> 5;
    int warp_m = (wid >> 2) * 64;
    int warp_n = (wid & 3) * 32;
    int row0 = blockIdx.x * BM, col0 = blockIdx.y * BN;
    int gid = lane >> 2;
    int tig = lane & 3;

    int a_row[2], b_kk[2], b_cb[2];
    const float *a_src[2], *b_src[2];
    unsigned a_dst[2], b_dst[2];
    int a_pred[2];
    unsigned baseA = (unsigned)__cvta_generic_to_shared(&sA[0][0][0]);
    unsigned baseB = (unsigned)__cvta_generic_to_shared(&sB[0][0][0]);
    const unsigned bufA = BM * ASTR * 4;
    const unsigned bufB = BKT * BSTR * 4;
    #pragma unroll
    for (int t = 0; t < 2; t++) {
        int i = tid + t * 256;
        a_row[t] = i >> 2;  int acb = (i & 3) * 4;
        a_src[t] = A + (size_t)(row0 + a_row[t]) * K + acb;
        a_dst[t] = baseA + (a_row[t] * ASTR + acb) * 4;
        a_pred[t] = (row0 + a_row[t] < n) ? 16 : 0;
        b_kk[t] = i >> 5;   b_cb[t] = (i & 31) * 4;
        b_src[t] = B + (size_t)b_kk[t] * M + col0 + b_cb[t];
        b_dst[t] = baseB + (b_kk[t] * BSTR + b_cb[t]) * 4;
    }

    float acc[4][4][4];
    #pragma unroll
    for (int mi = 0; mi < 4; mi++)
        #pragma unroll
        for (int ni = 0; ni < 4; ni++)
            #pragma unroll
            for (int c = 0; c < 4; c++) acc[mi][ni][c] = 0.f;

    const int NT = K / BKT;
    #pragma unroll
    for (int t = 0; t < 2; t++) {
        cp16(a_dst[t], a_src[t], a_pred[t]);
        cp16(b_dst[t], b_src[t], 16);
    }
    cp_commit();

    int buf = 0;
    for (int it = 0; it < NT; it++) {
        if (it + 1 < NT) {
            int koff = (it + 1) * BKT;
            unsigned bo = (unsigned)(buf ^ 1);
            #pragma unroll
            for (int t = 0; t < 2; t++) {
                cp16(a_dst[t] + bo * bufA, a_src[t] + koff, a_pred[t]);
                cp16(b_dst[t] + bo * bufB, b_src[t] + (size_t)koff * M, 16);
            }
            cp_commit();
            cp_wait1();
        } else {
            cp_wait0();
        }
        __syncthreads();

        #pragma unroll
        for (int kc = 0; kc < BKT; kc += 8) {
            unsigned af[4][4], bf[4][2];
            #pragma unroll
            for (int mi = 0; mi < 4; mi++) {
                int r = warp_m + mi * 16 + gid;
                int c = kc + tig;
                af[mi][0] = f2tf32(sA[buf][r][c]);
                af[mi][1] = f2tf32(sA[buf][r + 8][c]);
                af[mi][2] = f2tf32(sA[buf][r][c + 4]);
                af[mi][3] = f2tf32(sA[buf][r + 8][c + 4]);
            }
            #pragma unroll
            for (int ni = 0; ni < 4; ni++) {
                int cc = warp_n + ni * 8 + gid;
                int rr = kc + tig;
                bf[ni][0] = f2tf32(sB[buf][rr][cc]);
                bf[ni][1] = f2tf32(sB[buf][rr + 4][cc]);
            }
            #pragma unroll
            for (int mi = 0; mi < 4; mi++)
                #pragma unroll
                for (int ni = 0; ni < 4; ni++) {
                    asm volatile(
                        "mma.sync.aligned.m16n8k8.row.col.f32.tf32.tf32.f32 "
                        "{%0,%1,%2,%3}, {%4,%5,%6,%7}, {%8,%9}, {%0,%1,%2,%3};"
                        : "+f"(acc[mi][ni][0]), "+f"(acc[mi][ni][1]),
                          "+f"(acc[mi][ni][2]), "+f"(acc[mi][ni][3])
                        : "r"(af[mi][0]), "r"(af[mi][1]), "r"(af[mi][2]), "r"(af[mi][3]),
                          "r"(bf[ni][0]), "r"(bf[ni][1]));
                }
        }
        __syncthreads();
        buf ^= 1;
    }

    #pragma unroll
    for (int mi = 0; mi < 4; mi++) {
        int r = row0 + warp_m + mi * 16 + gid;
        #pragma unroll
        for (int ni = 0; ni < 4; ni++) {
            int c = col0 + warp_n + ni * 8 + 2 * tig;
            if (HOUT) {
                __half* C = (__half*)Cv;
                if (r < n)
                    *(__half2*)(C + (size_t)r * M + c) =
                        __floats2half2_rn(acc[mi][ni][0], acc[mi][ni][1]);
                if (r + 8 < n)
                    *(__half2*)(C + (size_t)(r + 8) * M + c) =
                        __floats2half2_rn(acc[mi][ni][2], acc[mi][ni][3]);
            } else {
                float* C = (float*)Cv;
                if (r < n)
                    *(float2*)(C + (size_t)r * M + c) =
                        make_float2(acc[mi][ni][0], acc[mi][ni][1]);
                if (r + 8 < n)
                    *(float2*)(C + (size_t)(r + 8) * M + c) =
                        make_float2(acc[mi][ni][2], acc[mi][ni][3]);
            }
        }
    }
}

// ================= per-node attention scalars (fp16 features) =================
__global__ __launch_bounds__(256) void alpha1_kernel(
    const float* __restrict__ a_src, const float* __restrict__ a_dst)
{
    int node = (blockIdx.x * blockDim.x + threadIdx.x) >> 5;
    int lane = threadIdx.x & 31;
    if (node >= NN) return;
    uint4 q = ((const uint4*)(g_h1h + (size_t)node * HH))[lane];
    float2 f0 = __half22float2(*(__half2*)&q.x);
    float2 f1 = __half22float2(*((__half2*)&q.x + 1));
    float2 f2 = __half22float2(*(__half2*)&q.z);
    float2 f3 = __half22float2(*((__half2*)&q.z + 1));
    float4 wa0 = *(const float4*)(a_src + 8 * lane);
    float4 wa1 = *(const float4*)(a_src + 8 * lane + 4);
    float4 wd0 = *(const float4*)(a_dst + 8 * lane);
    float4 wd1 = *(const float4*)(a_dst + 8 * lane + 4);
    float s = f0.x * wa0.x + f0.y * wa0.y + f1.x * wa0.z + f1.y * wa0.w
            + f2.x * wa1.x + f2.y * wa1.y + f3.x * wa1.z + f3.y * wa1.w;
    float d = f0.x * wd0.x + f0.y * wd0.y + f1.x * wd0.z + f1.y * wd0.w
            + f2.x * wd1.x + f2.y * wd1.y + f3.x * wd1.z + f3.y * wd1.w;
    #pragma unroll
    for (int off = 1; off < 8; off <<= 1) {
        s += __shfl_xor_sync(0xffffffffu, s, off);
        d += __shfl_xor_sync(0xffffffffu, d, off);
    }
    if ((lane & 7) == 0) {
        int head = lane >> 3;
        g_as1[node * 4 + head] = s;
        g_ad1[node * 4 + head] = d;
    }
}

__global__ __launch_bounds__(256) void alpha2_kernel(
    const float* __restrict__ a_src, const float* __restrict__ a_dst)
{
    int node = (blockIdx.x * blockDim.x + threadIdx.x) >> 5;
    int lane = threadIdx.x & 31;
    if (node >= NN) return;
    uint2 q = ((const uint2*)(g_h2ph + (size_t)node * ODIM))[lane];
    float2 f0 = __half22float2(*(__half2*)&q.x);
    float2 f1 = __half22float2(*(__half2*)&q.y);
    float4 wa = *(const float4*)(a_src + 4 * lane);
    float4 wd = *(const float4*)(a_dst + 4 * lane);
    float s = f0.x * wa.x + f0.y * wa.y + f1.x * wa.z + f1.y * wa.w;
    float d = f0.x * wd.x + f0.y * wd.y + f1.x * wd.z + f1.y * wd.w;
    s = warp_sum(s); d = warp_sum(d);
    if (lane == 0) { g_as2[node] = s; g_ad2[node] = d; }
}

// ================= fused layer1: softmax + aggregate + bias + ELU =================
// one warp per dst node; lane owns 8 contiguous features (head = lane>>3)
__global__ __launch_bounds__(256) void agg1_kernel(const float* __restrict__ b1)
{
    int node = blockIdx.x * 8 + (threadIdx.x >> 5);
    int lane = threadIdx.x & 31;
    if (node >= NN) return;
    int beg = g_off[node], end = g_off[node + 1];

    float4 ad = *(const float4*)&g_ad1[node * 4];

    float m0 = -1e30f, m1 = -1e30f, m2 = -1e30f, m3 = -1e30f;
    for (int i = beg + lane; i < end; i += 32) {
        int s = g_csr_src[i];
        float4 as = *(const float4*)&g_as1[s * 4];
        m0 = fmaxf(m0, lrelu(as.x + ad.x));
        m1 = fmaxf(m1, lrelu(as.y + ad.y));
        m2 = fmaxf(m2, lrelu(as.z + ad.z));
        m3 = fmaxf(m3, lrelu(as.w + ad.w));
    }
    m0 = warp_max(m0); m1 = warp_max(m1); m2 = warp_max(m2); m3 = warp_max(m3);

    int head = lane >> 3;
    float m_sel  = (head & 2) ? ((head & 1) ? m3 : m2) : ((head & 1) ? m1 : m0);
    float ad_sel = sel4(ad, head);

    float den0 = 0.f, den1 = 0.f, den2 = 0.f, den3 = 0.f;
    float a0 = 0.f, a1 = 0.f, a2 = 0.f, a3 = 0.f,
          a4 = 0.f, a5 = 0.f, a6 = 0.f, a7 = 0.f;
    int i = beg;
    for (; i + 4 <= end; i += 4) {
        int s0 = g_csr_src[i];
        int s1 = g_csr_src[i + 1];
        int s2 = g_csr_src[i + 2];
        int s3 = g_csr_src[i + 3];
        float4 as0 = *(const float4*)&g_as1[s0 * 4];
        float4 as1 = *(const float4*)&g_as1[s1 * 4];
        float4 as2 = *(const float4*)&g_as1[s2 * 4];
        float4 as3 = *(const float4*)&g_as1[s3 * 4];
        uint4 q0 = ((const uint4*)(g_h1h + (size_t)s0 * HH))[lane];
        uint4 q1 = ((const uint4*)(g_h1h + (size_t)s1 * HH))[lane];
        uint4 q2 = ((const uint4*)(g_h1h + (size_t)s2 * HH))[lane];
        uint4 q3 = ((const uint4*)(g_h1h + (size_t)s3 * HH))[lane];
        float p0 = __expf(lrelu(sel4(as0, head) + ad_sel) - m_sel);
        float p1 = __expf(lrelu(sel4(as1, head) + ad_sel) - m_sel);
        float p2 = __expf(lrelu(sel4(as2, head) + ad_sel) - m_sel);
        float p3 = __expf(lrelu(sel4(as3, head) + ad_sel) - m_sel);
        den0 += p0; den1 += p1; den2 += p2; den3 += p3;
        float2 v;
        v = __half22float2(*(__half2*)&q0.x);        a0 += p0 * v.x; a1 += p0 * v.y;
        v = __half22float2(*((__half2*)&q0.x + 1));  a2 += p0 * v.x; a3 += p0 * v.y;
        v = __half22float2(*(__half2*)&q0.z);        a4 += p0 * v.x; a5 += p0 * v.y;
        v = __half22float2(*((__half2*)&q0.z + 1));  a6 += p0 * v.x; a7 += p0 * v.y;
        v = __half22float2(*(__half2*)&q1.x);        a0 += p1 * v.x; a1 += p1 * v.y;
        v = __half22float2(*((__half2*)&q1.x + 1));  a2 += p1 * v.x; a3 += p1 * v.y;
        v = __half22float2(*(__half2*)&q1.z);        a4 += p1 * v.x; a5 += p1 * v.y;
        v = __half22float2(*((__half2*)&q1.z + 1));  a6 += p1 * v.x; a7 += p1 * v.y;
        v = __half22float2(*(__half2*)&q2.x);        a0 += p2 * v.x; a1 += p2 * v.y;
        v = __half22float2(*((__half2*)&q2.x + 1));  a2 += p2 * v.x; a3 += p2 * v.y;
        v = __half22float2(*(__half2*)&q2.z);        a4 += p2 * v.x; a5 += p2 * v.y;
        v = __half22float2(*((__half2*)&q2.z + 1));  a6 += p2 * v.x; a7 += p2 * v.y;
        v = __half22float2(*(__half2*)&q3.x);        a0 += p3 * v.x; a1 += p3 * v.y;
        v = __half22float2(*((__half2*)&q3.x + 1));  a2 += p3 * v.x; a3 += p3 * v.y;
        v = __half22float2(*(__half2*)&q3.z);        a4 += p3 * v.x; a5 += p3 * v.y;
        v = __half22float2(*((__half2*)&q3.z + 1));  a6 += p3 * v.x; a7 += p3 * v.y;
    }
    for (; i < end; i++) {
        int s0 = g_csr_src[i];
        float4 as0 = *(const float4*)&g_as1[s0 * 4];
        uint4 q0 = ((const uint4*)(g_h1h + (size_t)s0 * HH))[lane];
        float p0 = __expf(lrelu(sel4(as0, head) + ad_sel) - m_sel);
        den0 += p0;
        float2 v;
        v = __half22float2(*(__half2*)&q0.x);        a0 += p0 * v.x; a1 += p0 * v.y;
        v = __half22float2(*((__half2*)&q0.x + 1));  a2 += p0 * v.x; a3 += p0 * v.y;
        v = __half22float2(*(__half2*)&q0.z);        a4 += p0 * v.x; a5 += p0 * v.y;
        v = __half22float2(*((__half2*)&q0.z + 1));  a6 += p0 * v.x; a7 += p0 * v.y;
    }
    float iv = 1.f / (den0 + den1 + den2 + den3 + 1e-16f);
    float4 bb0 = *(const float4*)(b1 + 8 * lane);
    float4 bb1 = *(const float4*)(b1 + 8 * lane + 4);
    float o0 = a0 * iv + bb0.x, o1 = a1 * iv + bb0.y;
    float o2 = a2 * iv + bb0.z, o3 = a3 * iv + bb0.w;
    float o4 = a4 * iv + bb1.x, o5 = a5 * iv + bb1.y;
    float o6 = a6 * iv + bb1.z, o7 = a7 * iv + bb1.w;
    o0 = o0 > 0.f ? o0 : (__expf(o0) - 1.f);
    o1 = o1 > 0.f ? o1 : (__expf(o1) - 1.f);
    o2 = o2 > 0.f ? o2 : (__expf(o2) - 1.f);
    o3 = o3 > 0.f ? o3 : (__expf(o3) - 1.f);
    o4 = o4 > 0.f ? o4 : (__expf(o4) - 1.f);
    o5 = o5 > 0.f ? o5 : (__expf(o5) - 1.f);
    o6 = o6 > 0.f ? o6 : (__expf(o6) - 1.f);
    o7 = o7 > 0.f ? o7 : (__expf(o7) - 1.f);
    float* og = &g_agg1[(size_t)node * HH + 8 * lane];
    *(float4*)og       = make_float4(o0, o1, o2, o3);
    *(float4*)(og + 4) = make_float4(o4, o5, o6, o7);
}

// ================= fused layer2: softmax + aggregate + bias + L2 normalize ======
// lane owns 4 contiguous features
__global__ __launch_bounds__(256) void agg2_kernel(
    float* __restrict__ out, const float* __restrict__ b2)
{
    int node = blockIdx.x * 8 + (threadIdx.x >> 5);
    int lane = threadIdx.x & 31;
    if (node >= NN) return;
    int beg = g_off[node], end = g_off[node + 1];

    float ad = g_ad2[node];

    float m = -1e30f;
    for (int i = beg + lane; i < end; i += 32) {
        int s = g_csr_src[i];
        m = fmaxf(m, lrelu(g_as2[s] + ad));
    }
    m = warp_max(m);

    float den0 = 0.f, den1 = 0.f, den2 = 0.f, den3 = 0.f;
    float a0 = 0.f, a1 = 0.f, a2 = 0.f, a3 = 0.f;
    int i = beg;
    for (; i + 4 <= end; i += 4) {
        int s0 = g_csr_src[i];
        int s1 = g_csr_src[i + 1];
        int s2 = g_csr_src[i + 2];
        int s3 = g_csr_src[i + 3];
        float l0 = g_as2[s0], l1 = g_as2[s1], l2 = g_as2[s2], l3 = g_as2[s3];
        uint2 q0 = ((const uint2*)(g_h2ph + (size_t)s0 * ODIM))[lane];
        uint2 q1 = ((const uint2*)(g_h2ph + (size_t)s1 * ODIM))[lane];
        uint2 q2 = ((const uint2*)(g_h2ph + (size_t)s2 * ODIM))[lane];
        uint2 q3 = ((const uint2*)(g_h2ph + (size_t)s3 * ODIM))[lane];
        float p0 = __expf(lrelu(l0 + ad) - m);
        float p1 = __expf(lrelu(l1 + ad) - m);
        float p2 = __expf(lrelu(l2 + ad) - m);
        float p3 = __expf(lrelu(l3 + ad) - m);
        den0 += p0; den1 += p1; den2 += p2; den3 += p3;
        float2 v;
        v = __half22float2(*(__half2*)&q0.x); a0 += p0 * v.x; a1 += p0 * v.y;
        v = __half22float2(*(__half2*)&q0.y); a2 += p0 * v.x; a3 += p0 * v.y;
        v = __half22float2(*(__half2*)&q1.x); a0 += p1 * v.x; a1 += p1 * v.y;
        v = __half22float2(*(__half2*)&q1.y); a2 += p1 * v.x; a3 += p1 * v.y;
        v = __half22float2(*(__half2*)&q2.x); a0 += p2 * v.x; a1 += p2 * v.y;
        v = __half22float2(*(__half2*)&q2.y); a2 += p2 * v.x; a3 += p2 * v.y;
        v = __half22float2(*(__half2*)&q3.x); a0 += p3 * v.x; a1 += p3 * v.y;
        v = __half22float2(*(__half2*)&q3.y); a2 += p3 * v.x; a3 += p3 * v.y;
    }
    for (; i < end; i++) {
        int s0 = g_csr_src[i];
        uint2 q0 = ((const uint2*)(g_h2ph + (size_t)s0 * ODIM))[lane];
        float p0 = __expf(lrelu(g_as2[s0] + ad) - m);
        den0 += p0;
        float2 v;
        v = __half22float2(*(__half2*)&q0.x); a0 += p0 * v.x; a1 += p0 * v.y;
        v = __half22float2(*(__half2*)&q0.y); a2 += p0 * v.x; a3 += p0 * v.y;
    }
    float iv = 1.f / (den0 + den1 + den2 + den3 + 1e-16f);
    float4 b = *(const float4*)(b2 + 4 * lane);
    float4 v4;
    v4.x = a0 * iv + b.x; v4.y = a1 * iv + b.y;
    v4.z = a2 * iv + b.z; v4.w = a3 * iv + b.w;
    float ss = warp_sum(v4.x * v4.x + v4.y * v4.y + v4.z * v4.z + v4.w * v4.w);
    float sc = 1.f / fmaxf(sqrtf(ss), 1e-12f);
    v4.x *= sc; v4.y *= sc; v4.z *= sc; v4.w *= sc;
    *(float4*)(out + (size_t)node * ODIM + 4 * lane) = v4;
}

// ================= host =================
extern "C" void kernel_launch(void* const* d_in, const int* in_sizes, int n_in,
                              void* d_out, int out_size)
{
    const float* x      = (const float*)d_in[0];
    const int*   ei     = (const int*)d_in[1];     // int32 (JAX x64 disabled)
    const float* W1     = (const float*)d_in[2];
    const float* a_src1 = (const float*)d_in[3];
    const float* a_dst1 = (const float*)d_in[4];
    const float* b1     = (const float*)d_in[5];
    const float* W2     = (const float*)d_in[6];
    const float* a_src2 = (const float*)d_in[7];
    const float* a_dst2 = (const float*)d_in[8];
    const float* b2     = (const float*)d_in[9];
    float*       out    = (float*)d_out;
    const int*   srcp   = ei;
    const int*   dstp   = ei + NE;

    void* p_deg;
    cudaGetSymbolAddress(&p_deg, g_deg);
    void *p_h1h, *p_agg1, *p_h2ph;
    cudaGetSymbolAddress(&p_h1h,  g_h1h);
    cudaGetSymbolAddress(&p_agg1, g_agg1);
    cudaGetSymbolAddress(&p_h2ph, g_h2ph);

    cudaStream_t st = 0;
    const int EB = (TE + 255) / 256;
    const int MBLK = (NN + BM - 1) / BM;   // 391

    // fork-join: CSR build on side stream, layer1 projection on main stream.
    // Streams/events are created per call and intentionally NOT destroyed:
    // destroying a stream that participated in an active graph capture
    // invalidates the capture. kernel_launch is invoked only a handful of
    // times (correctness + capture), so the leak is bounded and harmless.
    cudaStream_t s2;
    cudaEvent_t evFork, evJoin;
    cudaStreamCreateWithFlags(&s2, cudaStreamNonBlocking);
    cudaEventCreateWithFlags(&evFork, cudaEventDisableTiming);
    cudaEventCreateWithFlags(&evJoin, cudaEventDisableTiming);

    cudaEventRecord(evFork, st);
    cudaStreamWaitEvent(s2, evFork, 0);

    // ---- side stream: CSR build (by dst) ----
    cudaMemsetAsync(p_deg, 0, sizeof(int) * NN, s2);
    hist_kernel<<<EB, 256, 0, s2>>>(srcp, dstp);
    scan_kernel<<<1, SCAN_T, 0, s2>>>();
    scatter_kernel<<<EB, 256, 0, s2>>>(srcp, dstp);
    cudaEventRecord(evJoin, s2);

    // ---- main stream: layer1 projection + alphas (independent of CSR) ----
    gemm_tf32_kernel<true><<<dim3(MBLK, 2), 256, 0, st>>>(x, W1, p_h1h, NN, IN_DIM, HH);
    alpha1_kernel<<<(NN * 32 + 255) / 256, 256, 0, st>>>(a_src1, a_dst1);

    // join: agg1 needs CSR + h1 + alphas
    cudaStreamWaitEvent(st, evJoin, 0);
    agg1_kernel<<<(NN + 7) / 8, 256, 0, st>>>(b1);

    // ---- layer 2 (serial chain) ----
    gemm_tf32_kernel<true><<<dim3(MBLK, 1), 256, 0, st>>>((const float*)p_agg1, W2,
                                                          p_h2ph, NN, HH, ODIM);
    alpha2_kernel<<<(NN * 32 + 255) / 256, 256, 0, st>>>(a_src2, a_dst2);
    agg2_kernel<<<(NN + 7) / 8, 256, 0, st>>>(out, b2);
}